// round 3
// baseline (speedup 1.0000x reference)
#include <cuda_runtime.h>
#include <cstdint>

// ---------------------------------------------------------------------------
// Problem constants
//   attention_input : [2, 4096, 1024] f32
//   attention_mask  : [2, 4096] f32 (values unused by reference)
//   permutation     : [256] int32  (gathers flattened (block,head) axis of K,V)
//   q_w/k_w/v_w     : [1024, 16, 64] f32  (== [1024,1024] row-major)
//   q_b/k_b/v_b     : [16, 64] f32        (== [1024])
//   output          : [2, 4096, 16, 64] f32
// ---------------------------------------------------------------------------

#define B_SZ     2
#define SEQ      4096
#define HID      1024
#define NH       16
#define HD       64
#define NB       16
#define BLK      256
#define MROWS    (B_SZ * SEQ)          // 8192

// Scratch for projected Q, K, V  (each [8192, 1024] f32)
__device__ float g_Q[MROWS * HID];
__device__ float g_K[MROWS * HID];
__device__ float g_V[MROWS * HID];

// ---------------------------------------------------------------------------
// Kernel 1: fused QKV projection.  C = A * W + b for W in {q_w,k_w,v_w}.
// 128x128x8 SGEMM, 256 threads, 8x8 microtile, register-prefetch pipeline.
// grid.x = 24 (3 matrices x 8 col-tiles), grid.y = 64 (row tiles)
// ---------------------------------------------------------------------------
__global__ __launch_bounds__(256) void sgemm_qkv(
    const float* __restrict__ A,
    const float* __restrict__ Wq, const float* __restrict__ Wk, const float* __restrict__ Wv,
    const float* __restrict__ bq, const float* __restrict__ bk, const float* __restrict__ bv)
{
    __shared__ float As[8][128];   // transposed A tile: As[k][m]
    __shared__ float Bs[8][128];   // B tile: Bs[k][n]

    const int which = blockIdx.x >> 3;             // 0=Q, 1=K, 2=V
    const int col0  = (blockIdx.x & 7) * 128;      // column tile within matrix
    const int row0  = blockIdx.y * 128;

    const float* W    = (which == 0) ? Wq : (which == 1) ? Wk : Wv;
    const float* bias = (which == 0) ? bq : (which == 1) ? bk : bv;
    float*       Out  = (which == 0) ? g_Q : (which == 1) ? g_K : g_V;

    const int tid = threadIdx.x;
    const int tx  = tid & 15;       // 0..15  (column group)
    const int ty  = tid >> 4;       // 0..15  (row group)

    // global-load assignments
    const int a_row  = tid >> 1;          // 0..127
    const int a_col4 = (tid & 1) * 4;     // 0 or 4
    const int b_row  = tid >> 5;          // 0..7
    const int b_col4 = (tid & 31) * 4;    // 0..124

    const float* Aptr = A + (size_t)(row0 + a_row) * HID + a_col4;
    const float* Bptr = W + (size_t)b_row * HID + col0 + b_col4;

    float acc[8][8];
    #pragma unroll
    for (int i = 0; i < 8; i++)
        #pragma unroll
        for (int j = 0; j < 8; j++) acc[i][j] = 0.0f;

    // prefetch first fragments
    float4 a_frag = *reinterpret_cast<const float4*>(Aptr);
    float4 b_frag = *reinterpret_cast<const float4*>(Bptr);

    for (int kt = 0; kt < HID; kt += 8) {
        As[a_col4 + 0][a_row] = a_frag.x;
        As[a_col4 + 1][a_row] = a_frag.y;
        As[a_col4 + 2][a_row] = a_frag.z;
        As[a_col4 + 3][a_row] = a_frag.w;
        *reinterpret_cast<float4*>(&Bs[b_row][b_col4]) = b_frag;
        __syncthreads();

        // prefetch next tile's fragments (overlaps with FFMA block below)
        const int kn = kt + 8;
        if (kn < HID) {
            a_frag = *reinterpret_cast<const float4*>(Aptr + kn);
            b_frag = *reinterpret_cast<const float4*>(Bptr + (size_t)kn * HID);
        }

        #pragma unroll
        for (int kk = 0; kk < 8; kk++) {
            float af[8], bf[8];
            *reinterpret_cast<float4*>(&af[0]) = *reinterpret_cast<const float4*>(&As[kk][ty * 4]);
            *reinterpret_cast<float4*>(&af[4]) = *reinterpret_cast<const float4*>(&As[kk][64 + ty * 4]);
            *reinterpret_cast<float4*>(&bf[0]) = *reinterpret_cast<const float4*>(&Bs[kk][tx * 4]);
            *reinterpret_cast<float4*>(&bf[4]) = *reinterpret_cast<const float4*>(&Bs[kk][64 + tx * 4]);
            #pragma unroll
            for (int i = 0; i < 8; i++)
                #pragma unroll
                for (int j = 0; j < 8; j++)
                    acc[i][j] += af[i] * bf[j];
        }
        __syncthreads();
    }

    // Epilogue: add bias, store.
    #pragma unroll
    for (int ii = 0; ii < 2; ii++) {
        #pragma unroll
        for (int i = 0; i < 4; i++) {
            const int row = row0 + ii * 64 + ty * 4 + i;
            float* orow = Out + (size_t)row * HID;
            #pragma unroll
            for (int jj = 0; jj < 2; jj++) {
                const int cm = col0 + jj * 64 + tx * 4;   // column within this matrix
                float4 r;
                r.x = acc[ii * 4 + i][jj * 4 + 0] + bias[cm + 0];
                r.y = acc[ii * 4 + i][jj * 4 + 1] + bias[cm + 1];
                r.z = acc[ii * 4 + i][jj * 4 + 2] + bias[cm + 2];
                r.w = acc[ii * 4 + i][jj * 4 + 3] + bias[cm + 3];
                *reinterpret_cast<float4*>(orow + cm) = r;
            }
        }
    }
}

// ---------------------------------------------------------------------------
// Kernel 2: block-local attention with permuted K/V gather.
// One CTA per (b, g, n): 256 threads, one query row per thread.
// K,V block [256,64] staged in dynamic smem (128 KB). Online softmax.
// grid = (n=16, g=16, b=2)
// ---------------------------------------------------------------------------
__global__ __launch_bounds__(256) void attn_kernel(
    const int* __restrict__ perm, float* __restrict__ out)
{
    extern __shared__ float smem[];
    float* Ks = smem;              // [256][64]
    float* Vs = smem + BLK * HD;   // [256][64]

    const int n = blockIdx.x;
    const int g = blockIdx.y;
    const int b = blockIdx.z;
    const int tid = threadIdx.x;

    const int p  = perm[g * NH + n];
    const int gs = p >> 4;          // source block
    const int ns = p & 15;          // source head

    const float* Ksrc = g_K + ((size_t)(b * SEQ + gs * BLK)) * HID + ns * HD;
    const float* Vsrc = g_V + ((size_t)(b * SEQ + gs * BLK)) * HID + ns * HD;

    // cooperative load: 256*16 float4 per matrix
    for (int idx = tid; idx < BLK * (HD / 4); idx += 256) {
        const int row = idx >> 4;
        const int c4  = (idx & 15) * 4;
        *reinterpret_cast<float4*>(Ks + row * HD + c4) =
            *reinterpret_cast<const float4*>(Ksrc + (size_t)row * HID + c4);
        *reinterpret_cast<float4*>(Vs + row * HD + c4) =
            *reinterpret_cast<const float4*>(Vsrc + (size_t)row * HID + c4);
    }
    __syncthreads();

    // load this thread's query row
    const float* qp = g_Q + ((size_t)(b * SEQ + g * BLK + tid)) * HID + n * HD;
    float4 q[16];
    #pragma unroll
    for (int i = 0; i < 16; i++)
        q[i] = *reinterpret_cast<const float4*>(qp + i * 4);

    float4 acc[16];
    #pragma unroll
    for (int i = 0; i < 16; i++) acc[i] = make_float4(0.f, 0.f, 0.f, 0.f);

    float mmax = -1e30f;
    float lsum = 0.0f;
    const float scale = 0.125f;   // 1/sqrt(64)

    for (int k = 0; k < BLK; k++) {
        const float4* kr = reinterpret_cast<const float4*>(Ks + k * HD);
        float s = 0.0f;
        #pragma unroll
        for (int i = 0; i < 16; i++) {
            float4 kv = kr[i];
            s += q[i].x * kv.x + q[i].y * kv.y + q[i].z * kv.z + q[i].w * kv.w;
        }
        s *= scale;

        const float4* vr = reinterpret_cast<const float4*>(Vs + k * HD);
        if (s > mmax) {
            const float corr = __expf(mmax - s);
            mmax = s;
            lsum = lsum * corr + 1.0f;
            #pragma unroll
            for (int i = 0; i < 16; i++) {
                float4 vv = vr[i];
                acc[i].x = acc[i].x * corr + vv.x;
                acc[i].y = acc[i].y * corr + vv.y;
                acc[i].z = acc[i].z * corr + vv.z;
                acc[i].w = acc[i].w * corr + vv.w;
            }
        } else {
            const float pw = __expf(s - mmax);
            lsum += pw;
            #pragma unroll
            for (int i = 0; i < 16; i++) {
                float4 vv = vr[i];
                acc[i].x += pw * vv.x;
                acc[i].y += pw * vv.y;
                acc[i].z += pw * vv.z;
                acc[i].w += pw * vv.w;
            }
        }
    }

    const float inv = 1.0f / lsum;
    // out[b, g*256+tid, n, :]  -> linear ((b*4096 + g*256 + tid)*16 + n)*64
    float* op = out + (((size_t)(b * SEQ + g * BLK + tid)) * NH + n) * HD;
    #pragma unroll
    for (int i = 0; i < 16; i++) {
        float4 r;
        r.x = acc[i].x * inv; r.y = acc[i].y * inv;
        r.z = acc[i].z * inv; r.w = acc[i].w * inv;
        *reinterpret_cast<float4*>(op + i * 4) = r;
    }
}

// ---------------------------------------------------------------------------
extern "C" void kernel_launch(void* const* d_in, const int* in_sizes, int n_in,
                              void* d_out, int out_size)
{
    const float* x    = (const float*)d_in[0];   // attention_input
    // d_in[1] = attention_mask (values unused by the reference)
    const int*   perm = (const int*)  d_in[2];
    const float* qw   = (const float*)d_in[3];
    const float* qb   = (const float*)d_in[4];
    const float* kw   = (const float*)d_in[5];
    const float* kb   = (const float*)d_in[6];
    const float* vw   = (const float*)d_in[7];
    const float* vb   = (const float*)d_in[8];
    float* out = (float*)d_out;

    dim3 ggrid(24, 64);
    sgemm_qkv<<<ggrid, 256>>>(x, qw, kw, vw, qb, kb, vb);

    const int smem_bytes = 2 * BLK * HD * sizeof(float);  // 128 KB
    (void)cudaFuncSetAttribute(attn_kernel, cudaFuncAttributeMaxDynamicSharedMemorySize, smem_bytes);
    attn_kernel<<<dim3(NH, NB, B_SZ), 256, smem_bytes>>>(perm, out);
}

// round 6
// speedup vs baseline: 1.4590x; 1.4590x over previous
#include <cuda_runtime.h>
#include <cuda_bf16.h>
#include <cstdint>

// ---------------------------------------------------------------------------
// SelfAttention: QKV projection (mma.sync bf16x3-split GEMM) + block-local
// permuted attention.  Plain sm_100 target: no tcgen05, use mma.sync/ldmatrix.
// ---------------------------------------------------------------------------

#define B_SZ     2
#define SEQ      4096
#define HID      1024
#define NH       16
#define HD       64
#define NB       16
#define BLK      256
#define MROWS    (B_SZ * SEQ)          // 8192

// fp32 projected Q/K/V
__device__ float g_Q[MROWS * HID];
__device__ float g_K[MROWS * HID];
__device__ float g_V[MROWS * HID];

// bf16 hi/lo split operands
__device__ __nv_bfloat16 g_Ah[MROWS * HID];
__device__ __nv_bfloat16 g_Al[MROWS * HID];
__device__ __nv_bfloat16 g_Wth[3 * HID * HID];   // transposed: [n][k]
__device__ __nv_bfloat16 g_Wtl[3 * HID * HID];

// ---------------------------------------------------------------------------
// PTX helpers (non-'a' features only: cp.async, ldmatrix, mma.sync)
// ---------------------------------------------------------------------------
__device__ __forceinline__ uint32_t smem_u32(const void* p) {
    uint32_t a;
    asm("{ .reg .u64 t; cvta.to.shared.u64 t, %1; cvt.u32.u64 %0, t; }"
        : "=r"(a) : "l"(p));
    return a;
}

__device__ __forceinline__ void cp16(uint32_t dst, const void* src) {
    asm volatile("cp.async.cg.shared.global [%0], [%1], 16;" :: "r"(dst), "l"(src));
}
#define CP_COMMIT() asm volatile("cp.async.commit_group;" ::: "memory")

__device__ __forceinline__ void ldm_x4(uint32_t* r, uint32_t addr) {
    asm volatile("ldmatrix.sync.aligned.m8n8.x4.shared.b16 {%0,%1,%2,%3}, [%4];"
                 : "=r"(r[0]), "=r"(r[1]), "=r"(r[2]), "=r"(r[3]) : "r"(addr));
}
__device__ __forceinline__ void ldm_x2(uint32_t* r, uint32_t addr) {
    asm volatile("ldmatrix.sync.aligned.m8n8.x2.shared.b16 {%0,%1}, [%2];"
                 : "=r"(r[0]), "=r"(r[1]) : "r"(addr));
}
__device__ __forceinline__ void mma_bf16(float* c, const uint32_t* a, const uint32_t* b) {
    asm volatile(
        "mma.sync.aligned.m16n8k16.row.col.f32.bf16.bf16.f32 "
        "{%0,%1,%2,%3}, {%4,%5,%6,%7}, {%8,%9}, {%0,%1,%2,%3};"
        : "+f"(c[0]), "+f"(c[1]), "+f"(c[2]), "+f"(c[3])
        : "r"(a[0]), "r"(a[1]), "r"(a[2]), "r"(a[3]), "r"(b[0]), "r"(b[1]));
}

// ---------------------------------------------------------------------------
// Pre-pass 1: split A into bf16 hi/lo
// ---------------------------------------------------------------------------
__global__ __launch_bounds__(256) void split_A_kernel(const float* __restrict__ x) {
    const int i = blockIdx.x * 256 + threadIdx.x;     // one float4 per thread
    float4 v = reinterpret_cast<const float4*>(x)[i];
    __nv_bfloat16 h0 = __float2bfloat16(v.x), h1 = __float2bfloat16(v.y);
    __nv_bfloat16 h2 = __float2bfloat16(v.z), h3 = __float2bfloat16(v.w);
    __nv_bfloat16 l0 = __float2bfloat16(v.x - __bfloat162float(h0));
    __nv_bfloat16 l1 = __float2bfloat16(v.y - __bfloat162float(h1));
    __nv_bfloat16 l2 = __float2bfloat16(v.z - __bfloat162float(h2));
    __nv_bfloat16 l3 = __float2bfloat16(v.w - __bfloat162float(h3));
    __nv_bfloat162* ph = reinterpret_cast<__nv_bfloat162*>(g_Ah) + 2 * i;
    __nv_bfloat162* pl = reinterpret_cast<__nv_bfloat162*>(g_Al) + 2 * i;
    __nv_bfloat162 t;
    t.x = h0; t.y = h1; ph[0] = t;
    t.x = h2; t.y = h3; ph[1] = t;
    t.x = l0; t.y = l1; pl[0] = t;
    t.x = l2; t.y = l3; pl[1] = t;
}

// ---------------------------------------------------------------------------
// Pre-pass 2: transpose + split weights.  wt[n][k] = w[k][n], hi/lo bf16.
// grid (32, 32, 3), block (32, 8)
// ---------------------------------------------------------------------------
__global__ __launch_bounds__(256) void split_W_kernel(
    const float* __restrict__ qw, const float* __restrict__ kw, const float* __restrict__ vw) {
    __shared__ float tile[32][33];
    const int mat = blockIdx.z;
    const float* src = (mat == 0) ? qw : (mat == 1) ? kw : vw;
    const int n0 = blockIdx.x * 32;
    const int k0 = blockIdx.y * 32;
    const int tx = threadIdx.x, ty = threadIdx.y;

    #pragma unroll
    for (int j = 0; j < 32; j += 8)
        tile[ty + j][tx] = src[(size_t)(k0 + ty + j) * HID + n0 + tx];
    __syncthreads();

    __nv_bfloat16* dh = g_Wth + (size_t)mat * HID * HID;
    __nv_bfloat16* dl = g_Wtl + (size_t)mat * HID * HID;
    #pragma unroll
    for (int j = 0; j < 32; j += 8) {
        float v = tile[tx][ty + j];
        __nv_bfloat16 h = __float2bfloat16(v);
        __nv_bfloat16 l = __float2bfloat16(v - __bfloat162float(h));
        dh[(size_t)(n0 + ty + j) * HID + k0 + tx] = h;
        dl[(size_t)(n0 + ty + j) * HID + k0 + tx] = l;
    }
}

// ---------------------------------------------------------------------------
// Main GEMM: C[8192, 3*1024] = A * Wt^T + bias, bf16x3 split via mma.sync.
// grid (24, 64), 256 threads (8 warps). CTA tile 128x128, K chunk 32.
// Warp grid 2(m) x 4(n): warp tile 64x32.
// smem per stage: 4 tiles (Ah, Al, Bh, Bl), each 128 rows x 80B (64B data
// + 16B pad -> ldmatrix conflict-free). Stage = 40960 B, double buffered.
// ---------------------------------------------------------------------------
#define ROW_B    80
#define TILE_B   (128 * ROW_B)            // 10240
#define STAGE_B  (4 * TILE_B)             // 40960
#define GEMM_SMEM (2 * STAGE_B)           // 81920

__device__ __forceinline__ void load_stage(
    uint32_t sstage, int row0, int nrow0, int kt, int tid) {
    const __nv_bfloat16* srcs[4] = {
        g_Ah  + (size_t)row0  * HID,
        g_Al  + (size_t)row0  * HID,
        g_Wth + (size_t)nrow0 * HID,
        g_Wtl + (size_t)nrow0 * HID };
    #pragma unroll
    for (int t = 0; t < 4; t++) {
        #pragma unroll
        for (int rep = 0; rep < 2; rep++) {
            const int idx = tid * 2 + rep;     // 0..511
            const int r = idx >> 2;
            const int u = idx & 3;
            cp16(sstage + t * TILE_B + r * ROW_B + u * 16,
                 srcs[t] + (size_t)r * HID + kt + u * 8);
        }
    }
    CP_COMMIT();
}

__global__ __launch_bounds__(256) void gemm_mma(
    const float* __restrict__ bq, const float* __restrict__ bk, const float* __restrict__ bv) {
    extern __shared__ __align__(128) char smem[];
    const uint32_t sb = smem_u32(smem);
    const int tid  = threadIdx.x;
    const int wid  = tid >> 5;
    const int lane = tid & 31;
    const int wm   = wid & 1;        // m half (0/1): rows wm*64
    const int wn   = wid >> 1;       // n quarter (0..3): cols wn*32

    const int t     = blockIdx.x;            // 0..23
    const int row0  = blockIdx.y * 128;
    const int which = t >> 3;
    const int nrow0 = t * 128;               // row into Wt (3072 rows)
    const int cm0   = (t & 7) * 128;         // col within matrix

    float acc[4][4][4];
    #pragma unroll
    for (int i = 0; i < 4; i++)
        #pragma unroll
        for (int j = 0; j < 4; j++)
            #pragma unroll
            for (int q = 0; q < 4; q++) acc[i][j][q] = 0.0f;

    // ldmatrix lane addressing (within a tile, per k-step)
    const int ag   = lane >> 3;              // 0..3 matrix group
    const int arow = (ag & 1) * 8 + (lane & 7);
    const int acu  = ag >> 1;                // k 16B-unit within step
    const int lb   = lane & 15;
    const int bg   = lb >> 3;
    const int brow = lb & 7;

    load_stage(sb, row0, nrow0, 0, tid);

    for (int c = 0; c < 32; c++) {
        if (c + 1 < 32) {
            load_stage(sb + ((c + 1) & 1) * STAGE_B, row0, nrow0, (c + 1) * 32, tid);
            asm volatile("cp.async.wait_group 1;" ::: "memory");
        } else {
            asm volatile("cp.async.wait_group 0;" ::: "memory");
        }
        __syncthreads();

        const uint32_t st  = sb + (c & 1) * STAGE_B;
        const uint32_t aAh = st + 0 * TILE_B;
        const uint32_t aAl = st + 1 * TILE_B;
        const uint32_t aBh = st + 2 * TILE_B;
        const uint32_t aBl = st + 3 * TILE_B;

        #pragma unroll
        for (int ks = 0; ks < 2; ks++) {
            uint32_t ah[4][4], al[4][4], bh[4][2], bl[4][2];
            #pragma unroll
            for (int i = 0; i < 4; i++) {
                const uint32_t off = (uint32_t)((wm * 64 + i * 16 + arow) * ROW_B
                                                + (2 * ks + acu) * 16);
                ldm_x4(ah[i], aAh + off);
                ldm_x4(al[i], aAl + off);
            }
            #pragma unroll
            for (int j = 0; j < 4; j++) {
                const uint32_t off = (uint32_t)((wn * 32 + j * 8 + brow) * ROW_B
                                                + (2 * ks + bg) * 16);
                ldm_x2(bh[j], aBh + off);
                ldm_x2(bl[j], aBl + off);
            }
            #pragma unroll
            for (int i = 0; i < 4; i++)
                #pragma unroll
                for (int j = 0; j < 4; j++) {
                    mma_bf16(acc[i][j], ah[i], bh[j]);
                    mma_bf16(acc[i][j], ah[i], bl[j]);
                    mma_bf16(acc[i][j], al[i], bh[j]);
                }
        }
        __syncthreads();
    }

    // Epilogue: bias + store fp32
    const float* bias = (which == 0) ? bq : (which == 1) ? bk : bv;
    float*       Out  = (which == 0) ? g_Q : (which == 1) ? g_K : g_V;
    const int r0 = lane >> 2;
    const int c0 = (lane & 3) * 2;
    #pragma unroll
    for (int i = 0; i < 4; i++) {
        const int m0 = row0 + wm * 64 + i * 16 + r0;
        #pragma unroll
        for (int j = 0; j < 4; j++) {
            const int col = cm0 + wn * 32 + j * 8 + c0;
            const float b0 = bias[col], b1 = bias[col + 1];
            float2 v0 = make_float2(acc[i][j][0] + b0, acc[i][j][1] + b1);
            float2 v1 = make_float2(acc[i][j][2] + b0, acc[i][j][3] + b1);
            *reinterpret_cast<float2*>(Out + (size_t)m0 * HID + col) = v0;
            *reinterpret_cast<float2*>(Out + (size_t)(m0 + 8) * HID + col) = v1;
        }
    }
}

// ---------------------------------------------------------------------------
// Kernel 2: block-local attention with permuted K/V gather (unchanged).
// ---------------------------------------------------------------------------
__global__ __launch_bounds__(256) void attn_kernel(
    const int* __restrict__ perm, float* __restrict__ out)
{
    extern __shared__ float smemf[];
    float* Ks = smemf;
    float* Vs = smemf + BLK * HD;

    const int n = blockIdx.x;
    const int g = blockIdx.y;
    const int b = blockIdx.z;
    const int tid = threadIdx.x;

    const int p  = perm[g * NH + n];
    const int gs = p >> 4;
    const int ns = p & 15;

    const float* Ksrc = g_K + ((size_t)(b * SEQ + gs * BLK)) * HID + ns * HD;
    const float* Vsrc = g_V + ((size_t)(b * SEQ + gs * BLK)) * HID + ns * HD;

    for (int idx = tid; idx < BLK * (HD / 4); idx += 256) {
        const int row = idx >> 4;
        const int c4  = (idx & 15) * 4;
        *reinterpret_cast<float4*>(Ks + row * HD + c4) =
            *reinterpret_cast<const float4*>(Ksrc + (size_t)row * HID + c4);
        *reinterpret_cast<float4*>(Vs + row * HD + c4) =
            *reinterpret_cast<const float4*>(Vsrc + (size_t)row * HID + c4);
    }
    __syncthreads();

    const float* qp = g_Q + ((size_t)(b * SEQ + g * BLK + tid)) * HID + n * HD;
    float4 q[16];
    #pragma unroll
    for (int i = 0; i < 16; i++)
        q[i] = *reinterpret_cast<const float4*>(qp + i * 4);

    float4 acc[16];
    #pragma unroll
    for (int i = 0; i < 16; i++) acc[i] = make_float4(0.f, 0.f, 0.f, 0.f);

    float mmax = -1e30f;
    float lsum = 0.0f;
    const float scale = 0.125f;

    for (int k = 0; k < BLK; k++) {
        const float4* kr = reinterpret_cast<const float4*>(Ks + k * HD);
        float s = 0.0f;
        #pragma unroll
        for (int i = 0; i < 16; i++) {
            float4 kv = kr[i];
            s += q[i].x * kv.x + q[i].y * kv.y + q[i].z * kv.z + q[i].w * kv.w;
        }
        s *= scale;

        const float4* vr = reinterpret_cast<const float4*>(Vs + k * HD);
        if (s > mmax) {
            const float corr = __expf(mmax - s);
            mmax = s;
            lsum = lsum * corr + 1.0f;
            #pragma unroll
            for (int i = 0; i < 16; i++) {
                float4 vv = vr[i];
                acc[i].x = acc[i].x * corr + vv.x;
                acc[i].y = acc[i].y * corr + vv.y;
                acc[i].z = acc[i].z * corr + vv.z;
                acc[i].w = acc[i].w * corr + vv.w;
            }
        } else {
            const float pw = __expf(s - mmax);
            lsum += pw;
            #pragma unroll
            for (int i = 0; i < 16; i++) {
                float4 vv = vr[i];
                acc[i].x += pw * vv.x;
                acc[i].y += pw * vv.y;
                acc[i].z += pw * vv.z;
                acc[i].w += pw * vv.w;
            }
        }
    }

    const float inv = 1.0f / lsum;
    float* op = out + (((size_t)(b * SEQ + g * BLK + tid)) * NH + n) * HD;
    #pragma unroll
    for (int i = 0; i < 16; i++) {
        float4 r;
        r.x = acc[i].x * inv; r.y = acc[i].y * inv;
        r.z = acc[i].z * inv; r.w = acc[i].w * inv;
        *reinterpret_cast<float4*>(op + i * 4) = r;
    }
}

// ---------------------------------------------------------------------------
extern "C" void kernel_launch(void* const* d_in, const int* in_sizes, int n_in,
                              void* d_out, int out_size)
{
    const float* x    = (const float*)d_in[0];
    const int*   perm = (const int*)  d_in[2];
    const float* qw   = (const float*)d_in[3];
    const float* qb   = (const float*)d_in[4];
    const float* kw   = (const float*)d_in[5];
    const float* kb   = (const float*)d_in[6];
    const float* vw   = (const float*)d_in[7];
    const float* vb   = (const float*)d_in[8];
    float* out = (float*)d_out;

    split_A_kernel<<<MROWS * HID / 4 / 256, 256>>>(x);
    split_W_kernel<<<dim3(32, 32, 3), dim3(32, 8)>>>(qw, kw, vw);

    (void)cudaFuncSetAttribute(gemm_mma, cudaFuncAttributeMaxDynamicSharedMemorySize, GEMM_SMEM);
    gemm_mma<<<dim3(24, 64), 256, GEMM_SMEM>>>(qb, kb, vb);

    const int smem_bytes = 2 * BLK * HD * sizeof(float);  // 128 KB
    (void)cudaFuncSetAttribute(attn_kernel, cudaFuncAttributeMaxDynamicSharedMemorySize, smem_bytes);
    attn_kernel<<<dim3(NH, NB, B_SZ), 256, smem_bytes>>>(perm, out);
}

// round 8
// speedup vs baseline: 2.0906x; 1.4329x over previous
#include <cuda_runtime.h>
#include <cuda_bf16.h>
#include <cstdint>

// ---------------------------------------------------------------------------
// SelfAttention: QKV projection (mma.sync bf16x3-split GEMM -> bf16 hi/lo
// outputs) + tensor-core block-local attention with permuted K/V gather.
// ---------------------------------------------------------------------------

#define B_SZ     2
#define SEQ      4096
#define HID      1024
#define NH       16
#define HD       64
#define NB       16
#define BLK      256
#define MROWS    (B_SZ * SEQ)          // 8192

// bf16 hi/lo split GEMM inputs
__device__ __nv_bfloat16 g_Ah[MROWS * HID];
__device__ __nv_bfloat16 g_Al[MROWS * HID];
__device__ __nv_bfloat16 g_Wth[3 * HID * HID];   // transposed: [n][k]
__device__ __nv_bfloat16 g_Wtl[3 * HID * HID];

// bf16 hi/lo projected Q/K/V (GEMM outputs)
__device__ __nv_bfloat16 g_Qh[MROWS * HID];
__device__ __nv_bfloat16 g_Ql[MROWS * HID];
__device__ __nv_bfloat16 g_Kh[MROWS * HID];
__device__ __nv_bfloat16 g_Kl[MROWS * HID];
__device__ __nv_bfloat16 g_Vh[MROWS * HID];
__device__ __nv_bfloat16 g_Vl[MROWS * HID];

// ---------------------------------------------------------------------------
// PTX helpers (non-'a' features only: cp.async, ldmatrix, mma.sync)
// ---------------------------------------------------------------------------
__device__ __forceinline__ uint32_t smem_u32(const void* p) {
    uint32_t a;
    asm("{ .reg .u64 t; cvta.to.shared.u64 t, %1; cvt.u32.u64 %0, t; }"
        : "=r"(a) : "l"(p));
    return a;
}

__device__ __forceinline__ void cp16(uint32_t dst, const void* src) {
    asm volatile("cp.async.cg.shared.global [%0], [%1], 16;" :: "r"(dst), "l"(src));
}
#define CP_COMMIT() asm volatile("cp.async.commit_group;" ::: "memory")

__device__ __forceinline__ void ldm_x4(uint32_t* r, uint32_t addr) {
    asm volatile("ldmatrix.sync.aligned.m8n8.x4.shared.b16 {%0,%1,%2,%3}, [%4];"
                 : "=r"(r[0]), "=r"(r[1]), "=r"(r[2]), "=r"(r[3]) : "r"(addr));
}
__device__ __forceinline__ void ldm_x2(uint32_t* r, uint32_t addr) {
    asm volatile("ldmatrix.sync.aligned.m8n8.x2.shared.b16 {%0,%1}, [%2];"
                 : "=r"(r[0]), "=r"(r[1]) : "r"(addr));
}
__device__ __forceinline__ void ldm_x2_t(uint32_t* r, uint32_t addr) {
    asm volatile("ldmatrix.sync.aligned.m8n8.x2.trans.shared.b16 {%0,%1}, [%2];"
                 : "=r"(r[0]), "=r"(r[1]) : "r"(addr));
}
__device__ __forceinline__ void mma_bf16(float* c, const uint32_t* a, const uint32_t* b) {
    asm volatile(
        "mma.sync.aligned.m16n8k16.row.col.f32.bf16.bf16.f32 "
        "{%0,%1,%2,%3}, {%4,%5,%6,%7}, {%8,%9}, {%0,%1,%2,%3};"
        : "+f"(c[0]), "+f"(c[1]), "+f"(c[2]), "+f"(c[3])
        : "r"(a[0]), "r"(a[1]), "r"(a[2]), "r"(a[3]), "r"(b[0]), "r"(b[1]));
}

// pack two floats -> bf16x2 (lo in low half)
__device__ __forceinline__ uint32_t pack_bf16(float lo, float hi) {
    uint32_t r;
    asm("cvt.rn.bf16x2.f32 %0, %1, %2;" : "=r"(r) : "f"(hi), "f"(lo));
    return r;
}
__device__ __forceinline__ float bf16_round(float x) {
    return __bfloat162float(__float2bfloat16(x));
}

// ---------------------------------------------------------------------------
// Pre-pass 1: split A into bf16 hi/lo
// ---------------------------------------------------------------------------
__global__ __launch_bounds__(256) void split_A_kernel(const float* __restrict__ x) {
    const int i = blockIdx.x * 256 + threadIdx.x;     // one float4 per thread
    float4 v = reinterpret_cast<const float4*>(x)[i];
    __nv_bfloat16 h0 = __float2bfloat16(v.x), h1 = __float2bfloat16(v.y);
    __nv_bfloat16 h2 = __float2bfloat16(v.z), h3 = __float2bfloat16(v.w);
    __nv_bfloat16 l0 = __float2bfloat16(v.x - __bfloat162float(h0));
    __nv_bfloat16 l1 = __float2bfloat16(v.y - __bfloat162float(h1));
    __nv_bfloat16 l2 = __float2bfloat16(v.z - __bfloat162float(h2));
    __nv_bfloat16 l3 = __float2bfloat16(v.w - __bfloat162float(h3));
    __nv_bfloat162* ph = reinterpret_cast<__nv_bfloat162*>(g_Ah) + 2 * i;
    __nv_bfloat162* pl = reinterpret_cast<__nv_bfloat162*>(g_Al) + 2 * i;
    __nv_bfloat162 t;
    t.x = h0; t.y = h1; ph[0] = t;
    t.x = h2; t.y = h3; ph[1] = t;
    t.x = l0; t.y = l1; pl[0] = t;
    t.x = l2; t.y = l3; pl[1] = t;
}

// ---------------------------------------------------------------------------
// Pre-pass 2: transpose + split weights.  wt[n][k] = w[k][n], hi/lo bf16.
// grid (32, 32, 3), block (32, 8)
// ---------------------------------------------------------------------------
__global__ __launch_bounds__(256) void split_W_kernel(
    const float* __restrict__ qw, const float* __restrict__ kw, const float* __restrict__ vw) {
    __shared__ float tile[32][33];
    const int mat = blockIdx.z;
    const float* src = (mat == 0) ? qw : (mat == 1) ? kw : vw;
    const int n0 = blockIdx.x * 32;
    const int k0 = blockIdx.y * 32;
    const int tx = threadIdx.x, ty = threadIdx.y;

    #pragma unroll
    for (int j = 0; j < 32; j += 8)
        tile[ty + j][tx] = src[(size_t)(k0 + ty + j) * HID + n0 + tx];
    __syncthreads();

    __nv_bfloat16* dh = g_Wth + (size_t)mat * HID * HID;
    __nv_bfloat16* dl = g_Wtl + (size_t)mat * HID * HID;
    #pragma unroll
    for (int j = 0; j < 32; j += 8) {
        float v = tile[tx][ty + j];
        __nv_bfloat16 h = __float2bfloat16(v);
        __nv_bfloat16 l = __float2bfloat16(v - __bfloat162float(h));
        dh[(size_t)(n0 + ty + j) * HID + k0 + tx] = h;
        dl[(size_t)(n0 + ty + j) * HID + k0 + tx] = l;
    }
}

// ---------------------------------------------------------------------------
// Main GEMM: C[8192, 3*1024] = A * Wt^T + bias, bf16x3 split via mma.sync.
// Epilogue stores bf16 hi/lo (for the tensor-core attention).
// ---------------------------------------------------------------------------
#define ROW_B    80
#define TILE_B   (128 * ROW_B)            // 10240
#define STAGE_B  (4 * TILE_B)             // 40960
#define GEMM_SMEM (2 * STAGE_B)           // 81920

__device__ __forceinline__ void load_stage(
    uint32_t sstage, int row0, int nrow0, int kt, int tid) {
    const __nv_bfloat16* srcs[4] = {
        g_Ah  + (size_t)row0  * HID,
        g_Al  + (size_t)row0  * HID,
        g_Wth + (size_t)nrow0 * HID,
        g_Wtl + (size_t)nrow0 * HID };
    #pragma unroll
    for (int t = 0; t < 4; t++) {
        #pragma unroll
        for (int rep = 0; rep < 2; rep++) {
            const int idx = tid * 2 + rep;     // 0..511
            const int r = idx >> 2;
            const int u = idx & 3;
            cp16(sstage + t * TILE_B + r * ROW_B + u * 16,
                 srcs[t] + (size_t)r * HID + kt + u * 8);
        }
    }
    CP_COMMIT();
}

__global__ __launch_bounds__(256) void gemm_mma(
    const float* __restrict__ bq, const float* __restrict__ bk, const float* __restrict__ bv) {
    extern __shared__ __align__(128) char smem[];
    const uint32_t sb = smem_u32(smem);
    const int tid  = threadIdx.x;
    const int wid  = tid >> 5;
    const int lane = tid & 31;
    const int wm   = wid & 1;
    const int wn   = wid >> 1;

    const int t     = blockIdx.x;            // 0..23
    const int row0  = blockIdx.y * 128;
    const int which = t >> 3;
    const int nrow0 = t * 128;
    const int cm0   = (t & 7) * 128;

    float acc[4][4][4];
    #pragma unroll
    for (int i = 0; i < 4; i++)
        #pragma unroll
        for (int j = 0; j < 4; j++)
            #pragma unroll
            for (int q = 0; q < 4; q++) acc[i][j][q] = 0.0f;

    const int ag   = lane >> 3;
    const int arow = (ag & 1) * 8 + (lane & 7);
    const int acu  = ag >> 1;
    const int lb   = lane & 15;
    const int bg   = lb >> 3;
    const int brow = lb & 7;

    load_stage(sb, row0, nrow0, 0, tid);

    for (int c = 0; c < 32; c++) {
        if (c + 1 < 32) {
            load_stage(sb + ((c + 1) & 1) * STAGE_B, row0, nrow0, (c + 1) * 32, tid);
            asm volatile("cp.async.wait_group 1;" ::: "memory");
        } else {
            asm volatile("cp.async.wait_group 0;" ::: "memory");
        }
        __syncthreads();

        const uint32_t st  = sb + (c & 1) * STAGE_B;
        const uint32_t aAh = st + 0 * TILE_B;
        const uint32_t aAl = st + 1 * TILE_B;
        const uint32_t aBh = st + 2 * TILE_B;
        const uint32_t aBl = st + 3 * TILE_B;

        #pragma unroll
        for (int ks = 0; ks < 2; ks++) {
            uint32_t ah[4][4], al[4][4], bh[4][2], bl[4][2];
            #pragma unroll
            for (int i = 0; i < 4; i++) {
                const uint32_t off = (uint32_t)((wm * 64 + i * 16 + arow) * ROW_B
                                                + (2 * ks + acu) * 16);
                ldm_x4(ah[i], aAh + off);
                ldm_x4(al[i], aAl + off);
            }
            #pragma unroll
            for (int j = 0; j < 4; j++) {
                const uint32_t off = (uint32_t)((wn * 32 + j * 8 + brow) * ROW_B
                                                + (2 * ks + bg) * 16);
                ldm_x2(bh[j], aBh + off);
                ldm_x2(bl[j], aBl + off);
            }
            #pragma unroll
            for (int i = 0; i < 4; i++)
                #pragma unroll
                for (int j = 0; j < 4; j++) {
                    mma_bf16(acc[i][j], ah[i], bh[j]);
                    mma_bf16(acc[i][j], ah[i], bl[j]);
                    mma_bf16(acc[i][j], al[i], bh[j]);
                }
        }
        __syncthreads();
    }

    // Epilogue: bias + split to bf16 hi/lo
    const float* bias = (which == 0) ? bq : (which == 1) ? bk : bv;
    __nv_bfloat16* Outh = (which == 0) ? g_Qh : (which == 1) ? g_Kh : g_Vh;
    __nv_bfloat16* Outl = (which == 0) ? g_Ql : (which == 1) ? g_Kl : g_Vl;
    const int r0 = lane >> 2;
    const int c0 = (lane & 3) * 2;
    #pragma unroll
    for (int i = 0; i < 4; i++) {
        const int m0 = row0 + wm * 64 + i * 16 + r0;
        #pragma unroll
        for (int j = 0; j < 4; j++) {
            const int col = cm0 + wn * 32 + j * 8 + c0;
            const float b0 = bias[col], b1 = bias[col + 1];
            const float v0 = acc[i][j][0] + b0, v1 = acc[i][j][1] + b1;
            const float v2 = acc[i][j][2] + b0, v3 = acc[i][j][3] + b1;
            *reinterpret_cast<uint32_t*>(Outh + (size_t)m0 * HID + col) = pack_bf16(v0, v1);
            *reinterpret_cast<uint32_t*>(Outl + (size_t)m0 * HID + col) =
                pack_bf16(v0 - bf16_round(v0), v1 - bf16_round(v1));
            *reinterpret_cast<uint32_t*>(Outh + (size_t)(m0 + 8) * HID + col) = pack_bf16(v2, v3);
            *reinterpret_cast<uint32_t*>(Outl + (size_t)(m0 + 8) * HID + col) =
                pack_bf16(v2 - bf16_round(v2), v3 - bf16_round(v3));
        }
    }
}

// ---------------------------------------------------------------------------
// Kernel 2: tensor-core block-local attention, bf16x3 split QK^T and PV,
// online softmax over 4 chunks of 64 keys. One CTA per (b, g, n), 8 warps,
// warp w owns query rows [w*32, w*32+32).
// ---------------------------------------------------------------------------
#define QSTR 144                          // smem row stride bytes (128 data + 16 pad)
#define SOFF_QH 0
#define SOFF_QL (256 * QSTR)              // 36864
#define SOFF_KH (2 * 256 * QSTR)          // 73728
#define SOFF_KL (SOFF_KH + 64 * QSTR)
#define SOFF_VH (SOFF_KL + 64 * QSTR)
#define SOFF_VL (SOFF_VH + 64 * QSTR)
#define ATTN_SMEM (SOFF_VL + 64 * QSTR)   // 110592

__global__ __launch_bounds__(256) void attn_mma(
    const int* __restrict__ perm, float* __restrict__ out)
{
    extern __shared__ __align__(128) char smem[];
    const uint32_t sb = smem_u32(smem);
    const int n = blockIdx.x, g = blockIdx.y, b = blockIdx.z;
    const int tid = threadIdx.x, wid = tid >> 5, lane = tid & 31;

    const int p  = perm[g * NH + n];
    const int gs = p >> 4;
    const int ns = p & 15;

    // load Q hi/lo into smem (256 rows x 8 x 16B units each)
    const size_t qbase = ((size_t)(b * SEQ + g * BLK)) * HID + n * HD;
    for (int i = tid; i < 2048; i += 256) {
        const int r = i >> 3, u = i & 7;
        *reinterpret_cast<uint4*>(smem + SOFF_QH + r * QSTR + u * 16) =
            *reinterpret_cast<const uint4*>(g_Qh + qbase + (size_t)r * HID + u * 8);
        *reinterpret_cast<uint4*>(smem + SOFF_QL + r * QSTR + u * 16) =
            *reinterpret_cast<const uint4*>(g_Ql + qbase + (size_t)r * HID + u * 8);
    }

    float m[2][2], l[2][2], oacc[2][8][4];
    #pragma unroll
    for (int mt = 0; mt < 2; mt++)
        #pragma unroll
        for (int h = 0; h < 2; h++) { m[mt][h] = -1e30f; l[mt][h] = 0.0f; }
    #pragma unroll
    for (int mt = 0; mt < 2; mt++)
        #pragma unroll
        for (int nt = 0; nt < 8; nt++)
            #pragma unroll
            for (int q = 0; q < 4; q++) oacc[mt][nt][q] = 0.0f;

    const int ag   = lane >> 3;
    const int arow = (ag & 1) * 8 + (lane & 7);
    const int acu  = ag >> 1;
    const int lb   = lane & 15;
    const int bg   = lb >> 3;
    const int brow = lb & 7;

    const size_t kvbase = ((size_t)(b * SEQ + gs * BLK)) * HID + ns * HD;

    for (int c = 0; c < 4; c++) {
        __syncthreads();   // Q visible (c=0); prior chunk compute done (c>0)
        for (int i = tid; i < 512; i += 256) {
            const int r = i >> 3, u = i & 7;
            const size_t go = kvbase + (size_t)(c * 64 + r) * HID + u * 8;
            *reinterpret_cast<uint4*>(smem + SOFF_KH + r * QSTR + u * 16) =
                *reinterpret_cast<const uint4*>(g_Kh + go);
            *reinterpret_cast<uint4*>(smem + SOFF_KL + r * QSTR + u * 16) =
                *reinterpret_cast<const uint4*>(g_Kl + go);
            *reinterpret_cast<uint4*>(smem + SOFF_VH + r * QSTR + u * 16) =
                *reinterpret_cast<const uint4*>(g_Vh + go);
            *reinterpret_cast<uint4*>(smem + SOFF_VL + r * QSTR + u * 16) =
                *reinterpret_cast<const uint4*>(g_Vl + go);
        }
        __syncthreads();

        // ---- S = Q K^T (bf16x3) ----
        float sacc[2][8][4];
        #pragma unroll
        for (int mt = 0; mt < 2; mt++)
            #pragma unroll
            for (int nt = 0; nt < 8; nt++)
                #pragma unroll
                for (int q = 0; q < 4; q++) sacc[mt][nt][q] = 0.0f;

        #pragma unroll
        for (int ks = 0; ks < 4; ks++) {
            uint32_t aqh[2][4], aql[2][4];
            #pragma unroll
            for (int mt = 0; mt < 2; mt++) {
                const uint32_t ao = sb + SOFF_QH
                    + (uint32_t)((wid * 32 + mt * 16 + arow) * QSTR + ks * 32 + acu * 16);
                ldm_x4(aqh[mt], ao);
                ldm_x4(aql[mt], ao + (SOFF_QL - SOFF_QH));
            }
            #pragma unroll
            for (int nt = 0; nt < 8; nt++) {
                uint32_t bkh[2], bkl[2];
                const uint32_t bo = sb + SOFF_KH
                    + (uint32_t)((nt * 8 + brow) * QSTR + ks * 32 + bg * 16);
                ldm_x2(bkh, bo);
                ldm_x2(bkl, bo + (SOFF_KL - SOFF_KH));
                #pragma unroll
                for (int mt = 0; mt < 2; mt++) {
                    mma_bf16(sacc[mt][nt], aqh[mt], bkh);
                    mma_bf16(sacc[mt][nt], aqh[mt], bkl);
                    mma_bf16(sacc[mt][nt], aql[mt], bkh);
                }
            }
        }

        // ---- online softmax ----
        #pragma unroll
        for (int mt = 0; mt < 2; mt++) {
            #pragma unroll
            for (int h = 0; h < 2; h++) {
                float rmax = -1e30f;
                #pragma unroll
                for (int nt = 0; nt < 8; nt++) {
                    sacc[mt][nt][2*h]   *= 0.125f;
                    sacc[mt][nt][2*h+1] *= 0.125f;
                    rmax = fmaxf(rmax, fmaxf(sacc[mt][nt][2*h], sacc[mt][nt][2*h+1]));
                }
                rmax = fmaxf(rmax, __shfl_xor_sync(0xffffffff, rmax, 1));
                rmax = fmaxf(rmax, __shfl_xor_sync(0xffffffff, rmax, 2));
                const float mn   = fmaxf(m[mt][h], rmax);
                const float corr = __expf(m[mt][h] - mn);
                m[mt][h] = mn;
                float rsum = 0.0f;
                #pragma unroll
                for (int nt = 0; nt < 8; nt++) {
                    const float e0 = __expf(sacc[mt][nt][2*h]   - mn);
                    const float e1 = __expf(sacc[mt][nt][2*h+1] - mn);
                    sacc[mt][nt][2*h] = e0; sacc[mt][nt][2*h+1] = e1;
                    rsum += e0 + e1;
                    oacc[mt][nt][2*h]   *= corr;
                    oacc[mt][nt][2*h+1] *= corr;
                }
                rsum += __shfl_xor_sync(0xffffffff, rsum, 1);
                rsum += __shfl_xor_sync(0xffffffff, rsum, 2);
                l[mt][h] = l[mt][h] * corr + rsum;
            }
        }

        // ---- O += P V (bf16x3; P frags from C-register layout) ----
        #pragma unroll
        for (int ks = 0; ks < 4; ks++) {
            uint32_t aph[2][4], apl[2][4];
            #pragma unroll
            for (int mt = 0; mt < 2; mt++) {
                #pragma unroll
                for (int half = 0; half < 2; half++) {   // n-tiles 2ks, 2ks+1
                    const float* s4 = sacc[mt][2 * ks + half];
                    aph[mt][2*half]     = pack_bf16(s4[0], s4[1]);
                    aph[mt][2*half + 1] = pack_bf16(s4[2], s4[3]);
                    apl[mt][2*half]     = pack_bf16(s4[0] - bf16_round(s4[0]),
                                                    s4[1] - bf16_round(s4[1]));
                    apl[mt][2*half + 1] = pack_bf16(s4[2] - bf16_round(s4[2]),
                                                    s4[3] - bf16_round(s4[3]));
                }
            }
            #pragma unroll
            for (int nd = 0; nd < 8; nd++) {
                uint32_t bvh[2], bvl[2];
                const uint32_t vo = sb + SOFF_VH
                    + (uint32_t)((ks * 16 + lb) * QSTR + nd * 16);
                ldm_x2_t(bvh, vo);
                ldm_x2_t(bvl, vo + (SOFF_VL - SOFF_VH));
                #pragma unroll
                for (int mt = 0; mt < 2; mt++) {
                    mma_bf16(oacc[mt][nd], aph[mt], bvh);
                    mma_bf16(oacc[mt][nd], aph[mt], bvl);
                    mma_bf16(oacc[mt][nd], apl[mt], bvh);
                }
            }
        }
    }

    // ---- write O / l ----
    const int lr = lane >> 2;
    const int lc = (lane & 3) * 2;
    #pragma unroll
    for (int mt = 0; mt < 2; mt++) {
        #pragma unroll
        for (int h = 0; h < 2; h++) {
            const float inv = 1.0f / l[mt][h];
            const int row = g * BLK + wid * 32 + mt * 16 + lr + 8 * h;
            float* op = out + (((size_t)(b * SEQ + row)) * NH + n) * HD;
            #pragma unroll
            for (int nd = 0; nd < 8; nd++) {
                float2 v = make_float2(oacc[mt][nd][2*h] * inv, oacc[mt][nd][2*h+1] * inv);
                *reinterpret_cast<float2*>(op + nd * 8 + lc) = v;
            }
        }
    }
}

// ---------------------------------------------------------------------------
extern "C" void kernel_launch(void* const* d_in, const int* in_sizes, int n_in,
                              void* d_out, int out_size)
{
    const float* x    = (const float*)d_in[0];
    const int*   perm = (const int*)  d_in[2];
    const float* qw   = (const float*)d_in[3];
    const float* qb   = (const float*)d_in[4];
    const float* kw   = (const float*)d_in[5];
    const float* kb   = (const float*)d_in[6];
    const float* vw   = (const float*)d_in[7];
    const float* vb   = (const float*)d_in[8];
    float* out = (float*)d_out;

    split_A_kernel<<<MROWS * HID / 4 / 256, 256>>>(x);
    split_W_kernel<<<dim3(32, 32, 3), dim3(32, 8)>>>(qw, kw, vw);

    (void)cudaFuncSetAttribute(gemm_mma, cudaFuncAttributeMaxDynamicSharedMemorySize, GEMM_SMEM);
    gemm_mma<<<dim3(24, 64), 256, GEMM_SMEM>>>(qb, kb, vb);

    (void)cudaFuncSetAttribute(attn_mma, cudaFuncAttributeMaxDynamicSharedMemorySize, ATTN_SMEM);
    attn_mma<<<dim3(NH, NB, B_SZ), 256, ATTN_SMEM>>>(perm, out);
}

// round 10
// speedup vs baseline: 2.0962x; 1.0027x over previous
#include <cuda_runtime.h>
#include <cuda_bf16.h>
#include <cstdint>

// ---------------------------------------------------------------------------
// SelfAttention: QKV projection (mma.sync bf16x3-split GEMM -> bf16 hi/lo
// outputs) + tensor-core block-local attention with permuted K/V gather.
// ---------------------------------------------------------------------------

#define B_SZ     2
#define SEQ      4096
#define HID      1024
#define NH       16
#define HD       64
#define NB       16
#define BLK      256
#define MROWS    (B_SZ * SEQ)          // 8192

// bf16 hi/lo split GEMM inputs
__device__ __nv_bfloat16 g_Ah[MROWS * HID];
__device__ __nv_bfloat16 g_Al[MROWS * HID];
__device__ __nv_bfloat16 g_Wth[3 * HID * HID];   // transposed: [n][k]
__device__ __nv_bfloat16 g_Wtl[3 * HID * HID];

// bf16 hi/lo projected Q/K/V (GEMM outputs)
__device__ __nv_bfloat16 g_Qh[MROWS * HID];
__device__ __nv_bfloat16 g_Ql[MROWS * HID];
__device__ __nv_bfloat16 g_Kh[MROWS * HID];
__device__ __nv_bfloat16 g_Kl[MROWS * HID];
__device__ __nv_bfloat16 g_Vh[MROWS * HID];
__device__ __nv_bfloat16 g_Vl[MROWS * HID];

// ---------------------------------------------------------------------------
// PTX helpers (non-'a' features only: cp.async, ldmatrix, mma.sync)
// ---------------------------------------------------------------------------
__device__ __forceinline__ uint32_t smem_u32(const void* p) {
    uint32_t a;
    asm("{ .reg .u64 t; cvta.to.shared.u64 t, %1; cvt.u32.u64 %0, t; }"
        : "=r"(a) : "l"(p));
    return a;
}

__device__ __forceinline__ void cp16(uint32_t dst, const void* src) {
    asm volatile("cp.async.cg.shared.global [%0], [%1], 16;" :: "r"(dst), "l"(src));
}
#define CP_COMMIT() asm volatile("cp.async.commit_group;" ::: "memory")

__device__ __forceinline__ void ldm_x4(uint32_t* r, uint32_t addr) {
    asm volatile("ldmatrix.sync.aligned.m8n8.x4.shared.b16 {%0,%1,%2,%3}, [%4];"
                 : "=r"(r[0]), "=r"(r[1]), "=r"(r[2]), "=r"(r[3]) : "r"(addr));
}
__device__ __forceinline__ void ldm_x2(uint32_t* r, uint32_t addr) {
    asm volatile("ldmatrix.sync.aligned.m8n8.x2.shared.b16 {%0,%1}, [%2];"
                 : "=r"(r[0]), "=r"(r[1]) : "r"(addr));
}
__device__ __forceinline__ void ldm_x2_t(uint32_t* r, uint32_t addr) {
    asm volatile("ldmatrix.sync.aligned.m8n8.x2.trans.shared.b16 {%0,%1}, [%2];"
                 : "=r"(r[0]), "=r"(r[1]) : "r"(addr));
}
__device__ __forceinline__ void mma_bf16(float* c, const uint32_t* a, const uint32_t* b) {
    asm volatile(
        "mma.sync.aligned.m16n8k16.row.col.f32.bf16.bf16.f32 "
        "{%0,%1,%2,%3}, {%4,%5,%6,%7}, {%8,%9}, {%0,%1,%2,%3};"
        : "+f"(c[0]), "+f"(c[1]), "+f"(c[2]), "+f"(c[3])
        : "r"(a[0]), "r"(a[1]), "r"(a[2]), "r"(a[3]), "r"(b[0]), "r"(b[1]));
}

// pack two floats -> bf16x2 (lo in low half)
__device__ __forceinline__ uint32_t pack_bf16(float lo, float hi) {
    uint32_t r;
    asm("cvt.rn.bf16x2.f32 %0, %1, %2;" : "=r"(r) : "f"(hi), "f"(lo));
    return r;
}
__device__ __forceinline__ float bf16_round(float x) {
    return __bfloat162float(__float2bfloat16(x));
}

// ---------------------------------------------------------------------------
// Pre-pass 1: split A into bf16 hi/lo
// ---------------------------------------------------------------------------
__global__ __launch_bounds__(256) void split_A_kernel(const float* __restrict__ x) {
    const int i = blockIdx.x * 256 + threadIdx.x;     // one float4 per thread
    float4 v = reinterpret_cast<const float4*>(x)[i];
    __nv_bfloat16 h0 = __float2bfloat16(v.x), h1 = __float2bfloat16(v.y);
    __nv_bfloat16 h2 = __float2bfloat16(v.z), h3 = __float2bfloat16(v.w);
    __nv_bfloat16 l0 = __float2bfloat16(v.x - __bfloat162float(h0));
    __nv_bfloat16 l1 = __float2bfloat16(v.y - __bfloat162float(h1));
    __nv_bfloat16 l2 = __float2bfloat16(v.z - __bfloat162float(h2));
    __nv_bfloat16 l3 = __float2bfloat16(v.w - __bfloat162float(h3));
    __nv_bfloat162* ph = reinterpret_cast<__nv_bfloat162*>(g_Ah) + 2 * i;
    __nv_bfloat162* pl = reinterpret_cast<__nv_bfloat162*>(g_Al) + 2 * i;
    __nv_bfloat162 t;
    t.x = h0; t.y = h1; ph[0] = t;
    t.x = h2; t.y = h3; ph[1] = t;
    t.x = l0; t.y = l1; pl[0] = t;
    t.x = l2; t.y = l3; pl[1] = t;
}

// ---------------------------------------------------------------------------
// Pre-pass 2: transpose + split weights.  wt[n][k] = w[k][n], hi/lo bf16.
// grid (32, 32, 3), block (32, 8)
// ---------------------------------------------------------------------------
__global__ __launch_bounds__(256) void split_W_kernel(
    const float* __restrict__ qw, const float* __restrict__ kw, const float* __restrict__ vw) {
    __shared__ float tile[32][33];
    const int mat = blockIdx.z;
    const float* src = (mat == 0) ? qw : (mat == 1) ? kw : vw;
    const int n0 = blockIdx.x * 32;
    const int k0 = blockIdx.y * 32;
    const int tx = threadIdx.x, ty = threadIdx.y;

    #pragma unroll
    for (int j = 0; j < 32; j += 8)
        tile[ty + j][tx] = src[(size_t)(k0 + ty + j) * HID + n0 + tx];
    __syncthreads();

    __nv_bfloat16* dh = g_Wth + (size_t)mat * HID * HID;
    __nv_bfloat16* dl = g_Wtl + (size_t)mat * HID * HID;
    #pragma unroll
    for (int j = 0; j < 32; j += 8) {
        float v = tile[tx][ty + j];
        __nv_bfloat16 h = __float2bfloat16(v);
        __nv_bfloat16 l = __float2bfloat16(v - __bfloat162float(h));
        dh[(size_t)(n0 + ty + j) * HID + k0 + tx] = h;
        dl[(size_t)(n0 + ty + j) * HID + k0 + tx] = l;
    }
}

// ---------------------------------------------------------------------------
// Main GEMM: C[8192, 3*1024] = A * Wt^T + bias, bf16x3 split via mma.sync.
// 512 threads (16 warps), CTA tile 128x128, warp tile 32x32 (4m x 4n grid),
// K chunk 32, 3-stage cp.async pipeline, one __syncthreads per chunk.
// Epilogue stores bf16 hi/lo (for the tensor-core attention).
// ---------------------------------------------------------------------------
#define ROW_B    80
#define TILE_B   (128 * ROW_B)            // 10240
#define STAGE_B  (4 * TILE_B)             // 40960
#define GEMM_SMEM (3 * STAGE_B)           // 122880

__device__ __forceinline__ void load_stage(
    uint32_t sstage, int row0, int nrow0, int kt, int tid) {
    const __nv_bfloat16* srcs[4] = {
        g_Ah  + (size_t)row0  * HID,
        g_Al  + (size_t)row0  * HID,
        g_Wth + (size_t)nrow0 * HID,
        g_Wtl + (size_t)nrow0 * HID };
    const int r = tid >> 2;               // 0..127
    const int u = tid & 3;                // 0..3 (16B units)
    #pragma unroll
    for (int t = 0; t < 4; t++) {
        cp16(sstage + t * TILE_B + r * ROW_B + u * 16,
             srcs[t] + (size_t)r * HID + kt + u * 8);
    }
    CP_COMMIT();
}

__global__ __launch_bounds__(512) void gemm_mma(
    const float* __restrict__ bq, const float* __restrict__ bk, const float* __restrict__ bv) {
    extern __shared__ __align__(128) char smem[];
    const uint32_t sb = smem_u32(smem);
    const int tid  = threadIdx.x;
    const int wid  = tid >> 5;           // 0..15
    const int lane = tid & 31;
    const int wm   = wid & 3;            // m quarter: rows wm*32
    const int wn   = wid >> 2;           // n quarter: cols wn*32

    const int t     = blockIdx.x;        // 0..23
    const int row0  = blockIdx.y * 128;
    const int which = t >> 3;
    const int nrow0 = t * 128;
    const int cm0   = (t & 7) * 128;

    float acc[2][4][4];
    #pragma unroll
    for (int i = 0; i < 2; i++)
        #pragma unroll
        for (int j = 0; j < 4; j++)
            #pragma unroll
            for (int q = 0; q < 4; q++) acc[i][j][q] = 0.0f;

    const int ag   = lane >> 3;
    const int arow = (ag & 1) * 8 + (lane & 7);
    const int acu  = ag >> 1;
    const int lb   = lane & 15;
    const int bg   = lb >> 3;
    const int brow = lb & 7;

    load_stage(sb + 0 * STAGE_B, row0, nrow0, 0,  tid);
    load_stage(sb + 1 * STAGE_B, row0, nrow0, 32, tid);

    int stage = 0;
    for (int c = 0; c < 32; c++) {
        if (c + 1 < 32) {
            asm volatile("cp.async.wait_group 1;" ::: "memory");
        } else {
            asm volatile("cp.async.wait_group 0;" ::: "memory");
        }
        __syncthreads();
        if (c + 2 < 32) {
            int ns = stage + 2; if (ns >= 3) ns -= 3;
            load_stage(sb + ns * STAGE_B, row0, nrow0, (c + 2) * 32, tid);
        }

        const uint32_t st  = sb + stage * STAGE_B;
        const uint32_t aAh = st + 0 * TILE_B;
        const uint32_t aAl = st + 1 * TILE_B;
        const uint32_t aBh = st + 2 * TILE_B;
        const uint32_t aBl = st + 3 * TILE_B;

        #pragma unroll
        for (int ks = 0; ks < 2; ks++) {
            uint32_t ah[2][4], al[2][4], bh[4][2], bl[4][2];
            #pragma unroll
            for (int i = 0; i < 2; i++) {
                const uint32_t off = (uint32_t)((wm * 32 + i * 16 + arow) * ROW_B
                                                + (2 * ks + acu) * 16);
                ldm_x4(ah[i], aAh + off);
                ldm_x4(al[i], aAl + off);
            }
            #pragma unroll
            for (int j = 0; j < 4; j++) {
                const uint32_t off = (uint32_t)((wn * 32 + j * 8 + brow) * ROW_B
                                                + (2 * ks + bg) * 16);
                ldm_x2(bh[j], aBh + off);
                ldm_x2(bl[j], aBl + off);
            }
            #pragma unroll
            for (int i = 0; i < 2; i++)
                #pragma unroll
                for (int j = 0; j < 4; j++) {
                    mma_bf16(acc[i][j], ah[i], bh[j]);
                    mma_bf16(acc[i][j], ah[i], bl[j]);
                    mma_bf16(acc[i][j], al[i], bh[j]);
                }
        }
        if (++stage >= 3) stage = 0;
    }

    // Epilogue: bias + split to bf16 hi/lo
    const float* bias = (which == 0) ? bq : (which == 1) ? bk : bv;
    __nv_bfloat16* Outh = (which == 0) ? g_Qh : (which == 1) ? g_Kh : g_Vh;
    __nv_bfloat16* Outl = (which == 0) ? g_Ql : (which == 1) ? g_Kl : g_Vl;
    const int r0 = lane >> 2;
    const int c0 = (lane & 3) * 2;
    #pragma unroll
    for (int i = 0; i < 2; i++) {
        const int m0 = row0 + wm * 32 + i * 16 + r0;
        #pragma unroll
        for (int j = 0; j < 4; j++) {
            const int col = cm0 + wn * 32 + j * 8 + c0;
            const float b0 = bias[col], b1 = bias[col + 1];
            const float v0 = acc[i][j][0] + b0, v1 = acc[i][j][1] + b1;
            const float v2 = acc[i][j][2] + b0, v3 = acc[i][j][3] + b1;
            *reinterpret_cast<uint32_t*>(Outh + (size_t)m0 * HID + col) = pack_bf16(v0, v1);
            *reinterpret_cast<uint32_t*>(Outl + (size_t)m0 * HID + col) =
                pack_bf16(v0 - bf16_round(v0), v1 - bf16_round(v1));
            *reinterpret_cast<uint32_t*>(Outh + (size_t)(m0 + 8) * HID + col) = pack_bf16(v2, v3);
            *reinterpret_cast<uint32_t*>(Outl + (size_t)(m0 + 8) * HID + col) =
                pack_bf16(v2 - bf16_round(v2), v3 - bf16_round(v3));
        }
    }
}

// ---------------------------------------------------------------------------
// Kernel 2: tensor-core block-local attention, bf16x3 split QK^T and PV,
// online softmax over 4 chunks of 64 keys. One CTA per (b, g, n), 8 warps,
// warp w owns query rows [w*32, w*32+32).  (unchanged from R8)
// ---------------------------------------------------------------------------
#define QSTR 144                          // smem row stride bytes (128 data + 16 pad)
#define SOFF_QH 0
#define SOFF_QL (256 * QSTR)              // 36864
#define SOFF_KH (2 * 256 * QSTR)          // 73728
#define SOFF_KL (SOFF_KH + 64 * QSTR)
#define SOFF_VH (SOFF_KL + 64 * QSTR)
#define SOFF_VL (SOFF_VH + 64 * QSTR)
#define ATTN_SMEM (SOFF_VL + 64 * QSTR)   // 110592

__global__ __launch_bounds__(256) void attn_mma(
    const int* __restrict__ perm, float* __restrict__ out)
{
    extern __shared__ __align__(128) char smem[];
    const uint32_t sb = smem_u32(smem);
    const int n = blockIdx.x, g = blockIdx.y, b = blockIdx.z;
    const int tid = threadIdx.x, wid = tid >> 5, lane = tid & 31;

    const int p  = perm[g * NH + n];
    const int gs = p >> 4;
    const int ns = p & 15;

    // load Q hi/lo into smem (256 rows x 8 x 16B units each)
    const size_t qbase = ((size_t)(b * SEQ + g * BLK)) * HID + n * HD;
    for (int i = tid; i < 2048; i += 256) {
        const int r = i >> 3, u = i & 7;
        *reinterpret_cast<uint4*>(smem + SOFF_QH + r * QSTR + u * 16) =
            *reinterpret_cast<const uint4*>(g_Qh + qbase + (size_t)r * HID + u * 8);
        *reinterpret_cast<uint4*>(smem + SOFF_QL + r * QSTR + u * 16) =
            *reinterpret_cast<const uint4*>(g_Ql + qbase + (size_t)r * HID + u * 8);
    }

    float m[2][2], l[2][2], oacc[2][8][4];
    #pragma unroll
    for (int mt = 0; mt < 2; mt++)
        #pragma unroll
        for (int h = 0; h < 2; h++) { m[mt][h] = -1e30f; l[mt][h] = 0.0f; }
    #pragma unroll
    for (int mt = 0; mt < 2; mt++)
        #pragma unroll
        for (int nt = 0; nt < 8; nt++)
            #pragma unroll
            for (int q = 0; q < 4; q++) oacc[mt][nt][q] = 0.0f;

    const int ag   = lane >> 3;
    const int arow = (ag & 1) * 8 + (lane & 7);
    const int acu  = ag >> 1;
    const int lb   = lane & 15;
    const int bg   = lb >> 3;
    const int brow = lb & 7;

    const size_t kvbase = ((size_t)(b * SEQ + gs * BLK)) * HID + ns * HD;

    for (int c = 0; c < 4; c++) {
        __syncthreads();   // Q visible (c=0); prior chunk compute done (c>0)
        for (int i = tid; i < 512; i += 256) {
            const int r = i >> 3, u = i & 7;
            const size_t go = kvbase + (size_t)(c * 64 + r) * HID + u * 8;
            *reinterpret_cast<uint4*>(smem + SOFF_KH + r * QSTR + u * 16) =
                *reinterpret_cast<const uint4*>(g_Kh + go);
            *reinterpret_cast<uint4*>(smem + SOFF_KL + r * QSTR + u * 16) =
                *reinterpret_cast<const uint4*>(g_Kl + go);
            *reinterpret_cast<uint4*>(smem + SOFF_VH + r * QSTR + u * 16) =
                *reinterpret_cast<const uint4*>(g_Vh + go);
            *reinterpret_cast<uint4*>(smem + SOFF_VL + r * QSTR + u * 16) =
                *reinterpret_cast<const uint4*>(g_Vl + go);
        }
        __syncthreads();

        // ---- S = Q K^T (bf16x3) ----
        float sacc[2][8][4];
        #pragma unroll
        for (int mt = 0; mt < 2; mt++)
            #pragma unroll
            for (int nt = 0; nt < 8; nt++)
                #pragma unroll
                for (int q = 0; q < 4; q++) sacc[mt][nt][q] = 0.0f;

        #pragma unroll
        for (int ks = 0; ks < 4; ks++) {
            uint32_t aqh[2][4], aql[2][4];
            #pragma unroll
            for (int mt = 0; mt < 2; mt++) {
                const uint32_t ao = sb + SOFF_QH
                    + (uint32_t)((wid * 32 + mt * 16 + arow) * QSTR + ks * 32 + acu * 16);
                ldm_x4(aqh[mt], ao);
                ldm_x4(aql[mt], ao + (SOFF_QL - SOFF_QH));
            }
            #pragma unroll
            for (int nt = 0; nt < 8; nt++) {
                uint32_t bkh[2], bkl[2];
                const uint32_t bo = sb + SOFF_KH
                    + (uint32_t)((nt * 8 + brow) * QSTR + ks * 32 + bg * 16);
                ldm_x2(bkh, bo);
                ldm_x2(bkl, bo + (SOFF_KL - SOFF_KH));
                #pragma unroll
                for (int mt = 0; mt < 2; mt++) {
                    mma_bf16(sacc[mt][nt], aqh[mt], bkh);
                    mma_bf16(sacc[mt][nt], aqh[mt], bkl);
                    mma_bf16(sacc[mt][nt], aql[mt], bkh);
                }
            }
        }

        // ---- online softmax ----
        #pragma unroll
        for (int mt = 0; mt < 2; mt++) {
            #pragma unroll
            for (int h = 0; h < 2; h++) {
                float rmax = -1e30f;
                #pragma unroll
                for (int nt = 0; nt < 8; nt++) {
                    sacc[mt][nt][2*h]   *= 0.125f;
                    sacc[mt][nt][2*h+1] *= 0.125f;
                    rmax = fmaxf(rmax, fmaxf(sacc[mt][nt][2*h], sacc[mt][nt][2*h+1]));
                }
                rmax = fmaxf(rmax, __shfl_xor_sync(0xffffffff, rmax, 1));
                rmax = fmaxf(rmax, __shfl_xor_sync(0xffffffff, rmax, 2));
                const float mn   = fmaxf(m[mt][h], rmax);
                const float corr = __expf(m[mt][h] - mn);
                m[mt][h] = mn;
                float rsum = 0.0f;
                #pragma unroll
                for (int nt = 0; nt < 8; nt++) {
                    const float e0 = __expf(sacc[mt][nt][2*h]   - mn);
                    const float e1 = __expf(sacc[mt][nt][2*h+1] - mn);
                    sacc[mt][nt][2*h] = e0; sacc[mt][nt][2*h+1] = e1;
                    rsum += e0 + e1;
                    oacc[mt][nt][2*h]   *= corr;
                    oacc[mt][nt][2*h+1] *= corr;
                }
                rsum += __shfl_xor_sync(0xffffffff, rsum, 1);
                rsum += __shfl_xor_sync(0xffffffff, rsum, 2);
                l[mt][h] = l[mt][h] * corr + rsum;
            }
        }

        // ---- O += P V (bf16x3; P frags from C-register layout) ----
        #pragma unroll
        for (int ks = 0; ks < 4; ks++) {
            uint32_t aph[2][4], apl[2][4];
            #pragma unroll
            for (int mt = 0; mt < 2; mt++) {
                #pragma unroll
                for (int half = 0; half < 2; half++) {   // n-tiles 2ks, 2ks+1
                    const float* s4 = sacc[mt][2 * ks + half];
                    aph[mt][2*half]     = pack_bf16(s4[0], s4[1]);
                    aph[mt][2*half + 1] = pack_bf16(s4[2], s4[3]);
                    apl[mt][2*half]     = pack_bf16(s4[0] - bf16_round(s4[0]),
                                                    s4[1] - bf16_round(s4[1]));
                    apl[mt][2*half + 1] = pack_bf16(s4[2] - bf16_round(s4[2]),
                                                    s4[3] - bf16_round(s4[3]));
                }
            }
            #pragma unroll
            for (int nd = 0; nd < 8; nd++) {
                uint32_t bvh[2], bvl[2];
                const uint32_t vo = sb + SOFF_VH
                    + (uint32_t)((ks * 16 + lb) * QSTR + nd * 16);
                ldm_x2_t(bvh, vo);
                ldm_x2_t(bvl, vo + (SOFF_VL - SOFF_VH));
                #pragma unroll
                for (int mt = 0; mt < 2; mt++) {
                    mma_bf16(oacc[mt][nd], aph[mt], bvh);
                    mma_bf16(oacc[mt][nd], aph[mt], bvl);
                    mma_bf16(oacc[mt][nd], apl[mt], bvh);
                }
            }
        }
    }

    // ---- write O / l ----
    const int lr = lane >> 2;
    const int lc = (lane & 3) * 2;
    #pragma unroll
    for (int mt = 0; mt < 2; mt++) {
        #pragma unroll
        for (int h = 0; h < 2; h++) {
            const float inv = 1.0f / l[mt][h];
            const int row = g * BLK + wid * 32 + mt * 16 + lr + 8 * h;
            float* op = out + (((size_t)(b * SEQ + row)) * NH + n) * HD;
            #pragma unroll
            for (int nd = 0; nd < 8; nd++) {
                float2 v = make_float2(oacc[mt][nd][2*h] * inv, oacc[mt][nd][2*h+1] * inv);
                *reinterpret_cast<float2*>(op + nd * 8 + lc) = v;
            }
        }
    }
}

// ---------------------------------------------------------------------------
extern "C" void kernel_launch(void* const* d_in, const int* in_sizes, int n_in,
                              void* d_out, int out_size)
{
    const float* x    = (const float*)d_in[0];
    const int*   perm = (const int*)  d_in[2];
    const float* qw   = (const float*)d_in[3];
    const float* qb   = (const float*)d_in[4];
    const float* kw   = (const float*)d_in[5];
    const float* kb   = (const float*)d_in[6];
    const float* vw   = (const float*)d_in[7];
    const float* vb   = (const float*)d_in[8];
    float* out = (float*)d_out;

    split_A_kernel<<<MROWS * HID / 4 / 256, 256>>>(x);
    split_W_kernel<<<dim3(32, 32, 3), dim3(32, 8)>>>(qw, kw, vw);

    (void)cudaFuncSetAttribute(gemm_mma, cudaFuncAttributeMaxDynamicSharedMemorySize, GEMM_SMEM);
    gemm_mma<<<dim3(24, 64), 512, GEMM_SMEM>>>(qb, kb, vb);

    (void)cudaFuncSetAttribute(attn_mma, cudaFuncAttributeMaxDynamicSharedMemorySize, ATTN_SMEM);
    attn_mma<<<dim3(NH, NB, B_SZ), 256, ATTN_SMEM>>>(perm, out);
}

// round 11
// speedup vs baseline: 3.0341x; 1.4475x over previous
#include <cuda_runtime.h>
#include <cuda_bf16.h>
#include <cuda_fp16.h>
#include <cstdint>

// ---------------------------------------------------------------------------
// SelfAttention: QKV projection (mma.sync fp16 2-term GEMM -> bf16 hi/lo
// outputs) + tensor-core block-local attention with permuted K/V gather.
// ---------------------------------------------------------------------------

#define B_SZ     2
#define SEQ      4096
#define HID      1024
#define NH       16
#define HD       64
#define NB       16
#define BLK      256
#define MROWS    (B_SZ * SEQ)          // 8192

// fp16 GEMM inputs: A split hi/lo (error-free), W single fp16 (transposed)
__device__ __half g_Ah[MROWS * HID];
__device__ __half g_Al[MROWS * HID];
__device__ __half g_Wt[3 * HID * HID];           // transposed: [n][k]

// bf16 hi/lo projected Q/K/V (GEMM outputs; attention inputs)
__device__ __nv_bfloat16 g_Qh[MROWS * HID];
__device__ __nv_bfloat16 g_Ql[MROWS * HID];
__device__ __nv_bfloat16 g_Kh[MROWS * HID];
__device__ __nv_bfloat16 g_Kl[MROWS * HID];
__device__ __nv_bfloat16 g_Vh[MROWS * HID];
__device__ __nv_bfloat16 g_Vl[MROWS * HID];

// ---------------------------------------------------------------------------
// PTX helpers (non-'a' features only: cp.async, ldmatrix, mma.sync)
// ---------------------------------------------------------------------------
__device__ __forceinline__ uint32_t smem_u32(const void* p) {
    uint32_t a;
    asm("{ .reg .u64 t; cvta.to.shared.u64 t, %1; cvt.u32.u64 %0, t; }"
        : "=r"(a) : "l"(p));
    return a;
}

__device__ __forceinline__ void cp16(uint32_t dst, const void* src) {
    asm volatile("cp.async.cg.shared.global [%0], [%1], 16;" :: "r"(dst), "l"(src));
}
#define CP_COMMIT() asm volatile("cp.async.commit_group;" ::: "memory")

__device__ __forceinline__ void ldm_x4(uint32_t* r, uint32_t addr) {
    asm volatile("ldmatrix.sync.aligned.m8n8.x4.shared.b16 {%0,%1,%2,%3}, [%4];"
                 : "=r"(r[0]), "=r"(r[1]), "=r"(r[2]), "=r"(r[3]) : "r"(addr));
}
__device__ __forceinline__ void ldm_x2(uint32_t* r, uint32_t addr) {
    asm volatile("ldmatrix.sync.aligned.m8n8.x2.shared.b16 {%0,%1}, [%2];"
                 : "=r"(r[0]), "=r"(r[1]) : "r"(addr));
}
__device__ __forceinline__ void ldm_x2_t(uint32_t* r, uint32_t addr) {
    asm volatile("ldmatrix.sync.aligned.m8n8.x2.trans.shared.b16 {%0,%1}, [%2];"
                 : "=r"(r[0]), "=r"(r[1]) : "r"(addr));
}
__device__ __forceinline__ void mma_bf16(float* c, const uint32_t* a, const uint32_t* b) {
    asm volatile(
        "mma.sync.aligned.m16n8k16.row.col.f32.bf16.bf16.f32 "
        "{%0,%1,%2,%3}, {%4,%5,%6,%7}, {%8,%9}, {%0,%1,%2,%3};"
        : "+f"(c[0]), "+f"(c[1]), "+f"(c[2]), "+f"(c[3])
        : "r"(a[0]), "r"(a[1]), "r"(a[2]), "r"(a[3]), "r"(b[0]), "r"(b[1]));
}
__device__ __forceinline__ void mma_fp16(float* c, const uint32_t* a, const uint32_t* b) {
    asm volatile(
        "mma.sync.aligned.m16n8k16.row.col.f32.f16.f16.f32 "
        "{%0,%1,%2,%3}, {%4,%5,%6,%7}, {%8,%9}, {%0,%1,%2,%3};"
        : "+f"(c[0]), "+f"(c[1]), "+f"(c[2]), "+f"(c[3])
        : "r"(a[0]), "r"(a[1]), "r"(a[2]), "r"(a[3]), "r"(b[0]), "r"(b[1]));
}

// pack two floats -> bf16x2 (lo in low half)
__device__ __forceinline__ uint32_t pack_bf16(float lo, float hi) {
    uint32_t r;
    asm("cvt.rn.bf16x2.f32 %0, %1, %2;" : "=r"(r) : "f"(hi), "f"(lo));
    return r;
}
__device__ __forceinline__ float bf16_round(float x) {
    return __bfloat162float(__float2bfloat16(x));
}

// ---------------------------------------------------------------------------
// Pre-pass 1: split A into fp16 hi/lo
// ---------------------------------------------------------------------------
__global__ __launch_bounds__(256) void split_A_kernel(const float* __restrict__ x) {
    const int i = blockIdx.x * 256 + threadIdx.x;     // one float4 per thread
    float4 v = reinterpret_cast<const float4*>(x)[i];
    __half h0 = __float2half(v.x), h1 = __float2half(v.y);
    __half h2 = __float2half(v.z), h3 = __float2half(v.w);
    __half l0 = __float2half(v.x - __half2float(h0));
    __half l1 = __float2half(v.y - __half2float(h1));
    __half l2 = __float2half(v.z - __half2float(h2));
    __half l3 = __float2half(v.w - __half2float(h3));
    __half2* ph = reinterpret_cast<__half2*>(g_Ah) + 2 * i;
    __half2* pl = reinterpret_cast<__half2*>(g_Al) + 2 * i;
    __half2 t;
    t.x = h0; t.y = h1; ph[0] = t;
    t.x = h2; t.y = h3; ph[1] = t;
    t.x = l0; t.y = l1; pl[0] = t;
    t.x = l2; t.y = l3; pl[1] = t;
}

// ---------------------------------------------------------------------------
// Pre-pass 2: transpose weights to fp16.  wt[n][k] = fp16(w[k][n]).
// grid (32, 32, 3), block (32, 8)
// ---------------------------------------------------------------------------
__global__ __launch_bounds__(256) void split_W_kernel(
    const float* __restrict__ qw, const float* __restrict__ kw, const float* __restrict__ vw) {
    __shared__ float tile[32][33];
    const int mat = blockIdx.z;
    const float* src = (mat == 0) ? qw : (mat == 1) ? kw : vw;
    const int n0 = blockIdx.x * 32;
    const int k0 = blockIdx.y * 32;
    const int tx = threadIdx.x, ty = threadIdx.y;

    #pragma unroll
    for (int j = 0; j < 32; j += 8)
        tile[ty + j][tx] = src[(size_t)(k0 + ty + j) * HID + n0 + tx];
    __syncthreads();

    __half* dh = g_Wt + (size_t)mat * HID * HID;
    #pragma unroll
    for (int j = 0; j < 32; j += 8)
        dh[(size_t)(n0 + ty + j) * HID + k0 + tx] = __float2half(tile[tx][ty + j]);
}

// ---------------------------------------------------------------------------
// Main GEMM: C[8192, 3*1024] = A * Wt^T + bias, fp16 2-term via mma.sync.
// 512 threads (16 warps), CTA tile 128x128, warp tile 32x32 (4m x 4n grid),
// K chunk 32, 3-stage cp.async pipeline, one __syncthreads per chunk.
// Stage = 3 tiles (Ah, Al, W).  Epilogue stores bf16 hi/lo.
// ---------------------------------------------------------------------------
#define ROW_B    80
#define TILE_B   (128 * ROW_B)            // 10240
#define STAGE_B  (3 * TILE_B)             // 30720
#define GEMM_SMEM (3 * STAGE_B)           // 92160

__device__ __forceinline__ void load_stage(
    uint32_t sstage, int row0, int nrow0, int kt, int tid) {
    const __half* srcs[3] = {
        g_Ah + (size_t)row0  * HID,
        g_Al + (size_t)row0  * HID,
        g_Wt + (size_t)nrow0 * HID };
    const int r = tid >> 2;               // 0..127
    const int u = tid & 3;                // 0..3 (16B units)
    #pragma unroll
    for (int t = 0; t < 3; t++) {
        cp16(sstage + t * TILE_B + r * ROW_B + u * 16,
             srcs[t] + (size_t)r * HID + kt + u * 8);
    }
    CP_COMMIT();
}

__global__ __launch_bounds__(512) void gemm_mma(
    const float* __restrict__ bq, const float* __restrict__ bk, const float* __restrict__ bv) {
    extern __shared__ __align__(128) char smem[];
    const uint32_t sb = smem_u32(smem);
    const int tid  = threadIdx.x;
    const int wid  = tid >> 5;           // 0..15
    const int lane = tid & 31;
    const int wm   = wid & 3;            // m quarter: rows wm*32
    const int wn   = wid >> 2;           // n quarter: cols wn*32

    const int t     = blockIdx.x;        // 0..23
    const int row0  = blockIdx.y * 128;
    const int which = t >> 3;
    const int nrow0 = t * 128;
    const int cm0   = (t & 7) * 128;

    float acc[2][4][4];
    #pragma unroll
    for (int i = 0; i < 2; i++)
        #pragma unroll
        for (int j = 0; j < 4; j++)
            #pragma unroll
            for (int q = 0; q < 4; q++) acc[i][j][q] = 0.0f;

    const int ag   = lane >> 3;
    const int arow = (ag & 1) * 8 + (lane & 7);
    const int acu  = ag >> 1;
    const int lb   = lane & 15;
    const int bg   = lb >> 3;
    const int brow = lb & 7;

    load_stage(sb + 0 * STAGE_B, row0, nrow0, 0,  tid);
    load_stage(sb + 1 * STAGE_B, row0, nrow0, 32, tid);

    int stage = 0;
    for (int c = 0; c < 32; c++) {
        if (c + 1 < 32) {
            asm volatile("cp.async.wait_group 1;" ::: "memory");
        } else {
            asm volatile("cp.async.wait_group 0;" ::: "memory");
        }
        __syncthreads();
        if (c + 2 < 32) {
            int ns = stage + 2; if (ns >= 3) ns -= 3;
            load_stage(sb + ns * STAGE_B, row0, nrow0, (c + 2) * 32, tid);
        }

        const uint32_t st  = sb + stage * STAGE_B;
        const uint32_t aAh = st + 0 * TILE_B;
        const uint32_t aAl = st + 1 * TILE_B;
        const uint32_t aB  = st + 2 * TILE_B;

        #pragma unroll
        for (int ks = 0; ks < 2; ks++) {
            uint32_t ah[2][4], al[2][4], bw[4][2];
            #pragma unroll
            for (int i = 0; i < 2; i++) {
                const uint32_t off = (uint32_t)((wm * 32 + i * 16 + arow) * ROW_B
                                                + (2 * ks + acu) * 16);
                ldm_x4(ah[i], aAh + off);
                ldm_x4(al[i], aAl + off);
            }
            #pragma unroll
            for (int j = 0; j < 4; j++) {
                const uint32_t off = (uint32_t)((wn * 32 + j * 8 + brow) * ROW_B
                                                + (2 * ks + bg) * 16);
                ldm_x2(bw[j], aB + off);
            }
            #pragma unroll
            for (int i = 0; i < 2; i++)
                #pragma unroll
                for (int j = 0; j < 4; j++) {
                    mma_fp16(acc[i][j], ah[i], bw[j]);
                    mma_fp16(acc[i][j], al[i], bw[j]);
                }
        }
        if (++stage >= 3) stage = 0;
    }

    // Epilogue: bias + split to bf16 hi/lo
    const float* bias = (which == 0) ? bq : (which == 1) ? bk : bv;
    __nv_bfloat16* Outh = (which == 0) ? g_Qh : (which == 1) ? g_Kh : g_Vh;
    __nv_bfloat16* Outl = (which == 0) ? g_Ql : (which == 1) ? g_Kl : g_Vl;
    const int r0 = lane >> 2;
    const int c0 = (lane & 3) * 2;
    #pragma unroll
    for (int i = 0; i < 2; i++) {
        const int m0 = row0 + wm * 32 + i * 16 + r0;
        #pragma unroll
        for (int j = 0; j < 4; j++) {
            const int col = cm0 + wn * 32 + j * 8 + c0;
            const float b0 = bias[col], b1 = bias[col + 1];
            const float v0 = acc[i][j][0] + b0, v1 = acc[i][j][1] + b1;
            const float v2 = acc[i][j][2] + b0, v3 = acc[i][j][3] + b1;
            *reinterpret_cast<uint32_t*>(Outh + (size_t)m0 * HID + col) = pack_bf16(v0, v1);
            *reinterpret_cast<uint32_t*>(Outl + (size_t)m0 * HID + col) =
                pack_bf16(v0 - bf16_round(v0), v1 - bf16_round(v1));
            *reinterpret_cast<uint32_t*>(Outh + (size_t)(m0 + 8) * HID + col) = pack_bf16(v2, v3);
            *reinterpret_cast<uint32_t*>(Outl + (size_t)(m0 + 8) * HID + col) =
                pack_bf16(v2 - bf16_round(v2), v3 - bf16_round(v3));
        }
    }
}

// ---------------------------------------------------------------------------
// Kernel 2: tensor-core block-local attention, bf16x3 split QK^T and PV,
// online softmax over 4 chunks of 64 keys. One CTA per (b, g, n), 8 warps,
// warp w owns query rows [w*32, w*32+32).  (unchanged from R8/R10)
// ---------------------------------------------------------------------------
#define QSTR 144                          // smem row stride bytes (128 data + 16 pad)
#define SOFF_QH 0
#define SOFF_QL (256 * QSTR)              // 36864
#define SOFF_KH (2 * 256 * QSTR)          // 73728
#define SOFF_KL (SOFF_KH + 64 * QSTR)
#define SOFF_VH (SOFF_KL + 64 * QSTR)
#define SOFF_VL (SOFF_VH + 64 * QSTR)
#define ATTN_SMEM (SOFF_VL + 64 * QSTR)   // 110592

__global__ __launch_bounds__(256) void attn_mma(
    const int* __restrict__ perm, float* __restrict__ out)
{
    extern __shared__ __align__(128) char smem[];
    const uint32_t sb = smem_u32(smem);
    const int n = blockIdx.x, g = blockIdx.y, b = blockIdx.z;
    const int tid = threadIdx.x, wid = tid >> 5, lane = tid & 31;

    const int p  = perm[g * NH + n];
    const int gs = p >> 4;
    const int ns = p & 15;

    // load Q hi/lo into smem (256 rows x 8 x 16B units each)
    const size_t qbase = ((size_t)(b * SEQ + g * BLK)) * HID + n * HD;
    for (int i = tid; i < 2048; i += 256) {
        const int r = i >> 3, u = i & 7;
        *reinterpret_cast<uint4*>(smem + SOFF_QH + r * QSTR + u * 16) =
            *reinterpret_cast<const uint4*>(g_Qh + qbase + (size_t)r * HID + u * 8);
        *reinterpret_cast<uint4*>(smem + SOFF_QL + r * QSTR + u * 16) =
            *reinterpret_cast<const uint4*>(g_Ql + qbase + (size_t)r * HID + u * 8);
    }

    float m[2][2], l[2][2], oacc[2][8][4];
    #pragma unroll
    for (int mt = 0; mt < 2; mt++)
        #pragma unroll
        for (int h = 0; h < 2; h++) { m[mt][h] = -1e30f; l[mt][h] = 0.0f; }
    #pragma unroll
    for (int mt = 0; mt < 2; mt++)
        #pragma unroll
        for (int nt = 0; nt < 8; nt++)
            #pragma unroll
            for (int q = 0; q < 4; q++) oacc[mt][nt][q] = 0.0f;

    const int ag   = lane >> 3;
    const int arow = (ag & 1) * 8 + (lane & 7);
    const int acu  = ag >> 1;
    const int lb   = lane & 15;
    const int bg   = lb >> 3;
    const int brow = lb & 7;

    const size_t kvbase = ((size_t)(b * SEQ + gs * BLK)) * HID + ns * HD;

    for (int c = 0; c < 4; c++) {
        __syncthreads();   // Q visible (c=0); prior chunk compute done (c>0)
        for (int i = tid; i < 512; i += 256) {
            const int r = i >> 3, u = i & 7;
            const size_t go = kvbase + (size_t)(c * 64 + r) * HID + u * 8;
            *reinterpret_cast<uint4*>(smem + SOFF_KH + r * QSTR + u * 16) =
                *reinterpret_cast<const uint4*>(g_Kh + go);
            *reinterpret_cast<uint4*>(smem + SOFF_KL + r * QSTR + u * 16) =
                *reinterpret_cast<const uint4*>(g_Kl + go);
            *reinterpret_cast<uint4*>(smem + SOFF_VH + r * QSTR + u * 16) =
                *reinterpret_cast<const uint4*>(g_Vh + go);
            *reinterpret_cast<uint4*>(smem + SOFF_VL + r * QSTR + u * 16) =
                *reinterpret_cast<const uint4*>(g_Vl + go);
        }
        __syncthreads();

        // ---- S = Q K^T (bf16x3) ----
        float sacc[2][8][4];
        #pragma unroll
        for (int mt = 0; mt < 2; mt++)
            #pragma unroll
            for (int nt = 0; nt < 8; nt++)
                #pragma unroll
                for (int q = 0; q < 4; q++) sacc[mt][nt][q] = 0.0f;

        #pragma unroll
        for (int ks = 0; ks < 4; ks++) {
            uint32_t aqh[2][4], aql[2][4];
            #pragma unroll
            for (int mt = 0; mt < 2; mt++) {
                const uint32_t ao = sb + SOFF_QH
                    + (uint32_t)((wid * 32 + mt * 16 + arow) * QSTR + ks * 32 + acu * 16);
                ldm_x4(aqh[mt], ao);
                ldm_x4(aql[mt], ao + (SOFF_QL - SOFF_QH));
            }
            #pragma unroll
            for (int nt = 0; nt < 8; nt++) {
                uint32_t bkh[2], bkl[2];
                const uint32_t bo = sb + SOFF_KH
                    + (uint32_t)((nt * 8 + brow) * QSTR + ks * 32 + bg * 16);
                ldm_x2(bkh, bo);
                ldm_x2(bkl, bo + (SOFF_KL - SOFF_KH));
                #pragma unroll
                for (int mt = 0; mt < 2; mt++) {
                    mma_bf16(sacc[mt][nt], aqh[mt], bkh);
                    mma_bf16(sacc[mt][nt], aqh[mt], bkl);
                    mma_bf16(sacc[mt][nt], aql[mt], bkh);
                }
            }
        }

        // ---- online softmax ----
        #pragma unroll
        for (int mt = 0; mt < 2; mt++) {
            #pragma unroll
            for (int h = 0; h < 2; h++) {
                float rmax = -1e30f;
                #pragma unroll
                for (int nt = 0; nt < 8; nt++) {
                    sacc[mt][nt][2*h]   *= 0.125f;
                    sacc[mt][nt][2*h+1] *= 0.125f;
                    rmax = fmaxf(rmax, fmaxf(sacc[mt][nt][2*h], sacc[mt][nt][2*h+1]));
                }
                rmax = fmaxf(rmax, __shfl_xor_sync(0xffffffff, rmax, 1));
                rmax = fmaxf(rmax, __shfl_xor_sync(0xffffffff, rmax, 2));
                const float mn   = fmaxf(m[mt][h], rmax);
                const float corr = __expf(m[mt][h] - mn);
                m[mt][h] = mn;
                float rsum = 0.0f;
                #pragma unroll
                for (int nt = 0; nt < 8; nt++) {
                    const float e0 = __expf(sacc[mt][nt][2*h]   - mn);
                    const float e1 = __expf(sacc[mt][nt][2*h+1] - mn);
                    sacc[mt][nt][2*h] = e0; sacc[mt][nt][2*h+1] = e1;
                    rsum += e0 + e1;
                    oacc[mt][nt][2*h]   *= corr;
                    oacc[mt][nt][2*h+1] *= corr;
                }
                rsum += __shfl_xor_sync(0xffffffff, rsum, 1);
                rsum += __shfl_xor_sync(0xffffffff, rsum, 2);
                l[mt][h] = l[mt][h] * corr + rsum;
            }
        }

        // ---- O += P V (bf16x3; P frags from C-register layout) ----
        #pragma unroll
        for (int ks = 0; ks < 4; ks++) {
            uint32_t aph[2][4], apl[2][4];
            #pragma unroll
            for (int mt = 0; mt < 2; mt++) {
                #pragma unroll
                for (int half = 0; half < 2; half++) {   // n-tiles 2ks, 2ks+1
                    const float* s4 = sacc[mt][2 * ks + half];
                    aph[mt][2*half]     = pack_bf16(s4[0], s4[1]);
                    aph[mt][2*half + 1] = pack_bf16(s4[2], s4[3]);
                    apl[mt][2*half]     = pack_bf16(s4[0] - bf16_round(s4[0]),
                                                    s4[1] - bf16_round(s4[1]));
                    apl[mt][2*half + 1] = pack_bf16(s4[2] - bf16_round(s4[2]),
                                                    s4[3] - bf16_round(s4[3]));
                }
            }
            #pragma unroll
            for (int nd = 0; nd < 8; nd++) {
                uint32_t bvh[2], bvl[2];
                const uint32_t vo = sb + SOFF_VH
                    + (uint32_t)((ks * 16 + lb) * QSTR + nd * 16);
                ldm_x2_t(bvh, vo);
                ldm_x2_t(bvl, vo + (SOFF_VL - SOFF_VH));
                #pragma unroll
                for (int mt = 0; mt < 2; mt++) {
                    mma_bf16(oacc[mt][nd], aph[mt], bvh);
                    mma_bf16(oacc[mt][nd], aph[mt], bvl);
                    mma_bf16(oacc[mt][nd], apl[mt], bvh);
                }
            }
        }
    }

    // ---- write O / l ----
    const int lr = lane >> 2;
    const int lc = (lane & 3) * 2;
    #pragma unroll
    for (int mt = 0; mt < 2; mt++) {
        #pragma unroll
        for (int h = 0; h < 2; h++) {
            const float inv = 1.0f / l[mt][h];
            const int row = g * BLK + wid * 32 + mt * 16 + lr + 8 * h;
            float* op = out + (((size_t)(b * SEQ + row)) * NH + n) * HD;
            #pragma unroll
            for (int nd = 0; nd < 8; nd++) {
                float2 v = make_float2(oacc[mt][nd][2*h] * inv, oacc[mt][nd][2*h+1] * inv);
                *reinterpret_cast<float2*>(op + nd * 8 + lc) = v;
            }
        }
    }
}

// ---------------------------------------------------------------------------
extern "C" void kernel_launch(void* const* d_in, const int* in_sizes, int n_in,
                              void* d_out, int out_size)
{
    const float* x    = (const float*)d_in[0];
    const int*   perm = (const int*)  d_in[2];
    const float* qw   = (const float*)d_in[3];
    const float* qb   = (const float*)d_in[4];
    const float* kw   = (const float*)d_in[5];
    const float* kb   = (const float*)d_in[6];
    const float* vw   = (const float*)d_in[7];
    const float* vb   = (const float*)d_in[8];
    float* out = (float*)d_out;

    split_A_kernel<<<MROWS * HID / 4 / 256, 256>>>(x);
    split_W_kernel<<<dim3(32, 32, 3), dim3(32, 8)>>>(qw, kw, vw);

    (void)cudaFuncSetAttribute(gemm_mma, cudaFuncAttributeMaxDynamicSharedMemorySize, GEMM_SMEM);
    gemm_mma<<<dim3(24, 64), 512, GEMM_SMEM>>>(qb, kb, vb);

    (void)cudaFuncSetAttribute(attn_mma, cudaFuncAttributeMaxDynamicSharedMemorySize, ATTN_SMEM);
    attn_mma<<<dim3(NH, NB, B_SZ), 256, ATTN_SMEM>>>(perm, out);
}

// round 12
// speedup vs baseline: 3.8627x; 1.2731x over previous
#include <cuda_runtime.h>
#include <cuda_bf16.h>
#include <cuda_fp16.h>
#include <cstdint>

// ---------------------------------------------------------------------------
// SelfAttention: QKV projection (mma.sync single-fp16 GEMM -> bf16 hi/lo
// outputs) + tensor-core block-local attention with permuted K/V gather.
// ---------------------------------------------------------------------------

#define B_SZ     2
#define SEQ      4096
#define HID      1024
#define NH       16
#define HD       64
#define NB       16
#define BLK      256
#define MROWS    (B_SZ * SEQ)          // 8192

// fp16 GEMM inputs: A single fp16, W single fp16 (transposed)
__device__ __half g_Ah[MROWS * HID];
__device__ __half g_Wt[3 * HID * HID];           // transposed: [n][k]

// bf16 hi/lo projected Q/K/V (GEMM outputs; attention inputs)
__device__ __nv_bfloat16 g_Qh[MROWS * HID];
__device__ __nv_bfloat16 g_Ql[MROWS * HID];
__device__ __nv_bfloat16 g_Kh[MROWS * HID];
__device__ __nv_bfloat16 g_Kl[MROWS * HID];
__device__ __nv_bfloat16 g_Vh[MROWS * HID];
__device__ __nv_bfloat16 g_Vl[MROWS * HID];

// ---------------------------------------------------------------------------
// PTX helpers (non-'a' features only: cp.async, ldmatrix, mma.sync)
// ---------------------------------------------------------------------------
__device__ __forceinline__ uint32_t smem_u32(const void* p) {
    uint32_t a;
    asm("{ .reg .u64 t; cvta.to.shared.u64 t, %1; cvt.u32.u64 %0, t; }"
        : "=r"(a) : "l"(p));
    return a;
}

__device__ __forceinline__ void cp16(uint32_t dst, const void* src) {
    asm volatile("cp.async.cg.shared.global [%0], [%1], 16;" :: "r"(dst), "l"(src));
}
#define CP_COMMIT() asm volatile("cp.async.commit_group;" ::: "memory")

__device__ __forceinline__ void ldm_x4(uint32_t* r, uint32_t addr) {
    asm volatile("ldmatrix.sync.aligned.m8n8.x4.shared.b16 {%0,%1,%2,%3}, [%4];"
                 : "=r"(r[0]), "=r"(r[1]), "=r"(r[2]), "=r"(r[3]) : "r"(addr));
}
__device__ __forceinline__ void ldm_x2(uint32_t* r, uint32_t addr) {
    asm volatile("ldmatrix.sync.aligned.m8n8.x2.shared.b16 {%0,%1}, [%2];"
                 : "=r"(r[0]), "=r"(r[1]) : "r"(addr));
}
__device__ __forceinline__ void ldm_x2_t(uint32_t* r, uint32_t addr) {
    asm volatile("ldmatrix.sync.aligned.m8n8.x2.trans.shared.b16 {%0,%1}, [%2];"
                 : "=r"(r[0]), "=r"(r[1]) : "r"(addr));
}
__device__ __forceinline__ void mma_bf16(float* c, const uint32_t* a, const uint32_t* b) {
    asm volatile(
        "mma.sync.aligned.m16n8k16.row.col.f32.bf16.bf16.f32 "
        "{%0,%1,%2,%3}, {%4,%5,%6,%7}, {%8,%9}, {%0,%1,%2,%3};"
        : "+f"(c[0]), "+f"(c[1]), "+f"(c[2]), "+f"(c[3])
        : "r"(a[0]), "r"(a[1]), "r"(a[2]), "r"(a[3]), "r"(b[0]), "r"(b[1]));
}
__device__ __forceinline__ void mma_fp16(float* c, const uint32_t* a, const uint32_t* b) {
    asm volatile(
        "mma.sync.aligned.m16n8k16.row.col.f32.f16.f16.f32 "
        "{%0,%1,%2,%3}, {%4,%5,%6,%7}, {%8,%9}, {%0,%1,%2,%3};"
        : "+f"(c[0]), "+f"(c[1]), "+f"(c[2]), "+f"(c[3])
        : "r"(a[0]), "r"(a[1]), "r"(a[2]), "r"(a[3]), "r"(b[0]), "r"(b[1]));
}

// pack two floats -> bf16x2 (lo in low half)
__device__ __forceinline__ uint32_t pack_bf16(float lo, float hi) {
    uint32_t r;
    asm("cvt.rn.bf16x2.f32 %0, %1, %2;" : "=r"(r) : "f"(hi), "f"(lo));
    return r;
}
__device__ __forceinline__ float bf16_round(float x) {
    return __bfloat162float(__float2bfloat16(x));
}

// ---------------------------------------------------------------------------
// Pre-pass 1: convert A to fp16
// ---------------------------------------------------------------------------
__global__ __launch_bounds__(256) void split_A_kernel(const float* __restrict__ x) {
    const int i = blockIdx.x * 256 + threadIdx.x;     // one float4 per thread
    float4 v = reinterpret_cast<const float4*>(x)[i];
    __half2* ph = reinterpret_cast<__half2*>(g_Ah) + 2 * i;
    __half2 t0, t1;
    t0.x = __float2half(v.x); t0.y = __float2half(v.y);
    t1.x = __float2half(v.z); t1.y = __float2half(v.w);
    ph[0] = t0;
    ph[1] = t1;
}

// ---------------------------------------------------------------------------
// Pre-pass 2: transpose weights to fp16.  wt[n][k] = fp16(w[k][n]).
// grid (32, 32, 3), block (32, 8)
// ---------------------------------------------------------------------------
__global__ __launch_bounds__(256) void split_W_kernel(
    const float* __restrict__ qw, const float* __restrict__ kw, const float* __restrict__ vw) {
    __shared__ float tile[32][33];
    const int mat = blockIdx.z;
    const float* src = (mat == 0) ? qw : (mat == 1) ? kw : vw;
    const int n0 = blockIdx.x * 32;
    const int k0 = blockIdx.y * 32;
    const int tx = threadIdx.x, ty = threadIdx.y;

    #pragma unroll
    for (int j = 0; j < 32; j += 8)
        tile[ty + j][tx] = src[(size_t)(k0 + ty + j) * HID + n0 + tx];
    __syncthreads();

    __half* dh = g_Wt + (size_t)mat * HID * HID;
    #pragma unroll
    for (int j = 0; j < 32; j += 8)
        dh[(size_t)(n0 + ty + j) * HID + k0 + tx] = __float2half(tile[tx][ty + j]);
}

// ---------------------------------------------------------------------------
// Main GEMM: C[8192, 3*1024] = A * Wt^T + bias, single fp16 via mma.sync.
// 512 threads (16 warps), CTA tile 128x128, warp tile 32x32 (4m x 4n grid),
// K chunk 32, 3-stage cp.async pipeline, one __syncthreads per chunk.
// Stage = 2 tiles (A, W).  Epilogue stores bf16 hi/lo.
// ---------------------------------------------------------------------------
#define ROW_B    80
#define TILE_B   (128 * ROW_B)            // 10240
#define STAGE_B  (2 * TILE_B)             // 20480
#define GEMM_SMEM (3 * STAGE_B)           // 61440

__device__ __forceinline__ void load_stage(
    uint32_t sstage, int row0, int nrow0, int kt, int tid) {
    const __half* srcs[2] = {
        g_Ah + (size_t)row0  * HID,
        g_Wt + (size_t)nrow0 * HID };
    const int r = tid >> 2;               // 0..127
    const int u = tid & 3;                // 0..3 (16B units)
    #pragma unroll
    for (int t = 0; t < 2; t++) {
        cp16(sstage + t * TILE_B + r * ROW_B + u * 16,
             srcs[t] + (size_t)r * HID + kt + u * 8);
    }
    CP_COMMIT();
}

__global__ __launch_bounds__(512) void gemm_mma(
    const float* __restrict__ bq, const float* __restrict__ bk, const float* __restrict__ bv) {
    extern __shared__ __align__(128) char smem[];
    const uint32_t sb = smem_u32(smem);
    const int tid  = threadIdx.x;
    const int wid  = tid >> 5;           // 0..15
    const int lane = tid & 31;
    const int wm   = wid & 3;            // m quarter: rows wm*32
    const int wn   = wid >> 2;           // n quarter: cols wn*32

    const int t     = blockIdx.x;        // 0..23
    const int row0  = blockIdx.y * 128;
    const int which = t >> 3;
    const int nrow0 = t * 128;
    const int cm0   = (t & 7) * 128;

    float acc[2][4][4];
    #pragma unroll
    for (int i = 0; i < 2; i++)
        #pragma unroll
        for (int j = 0; j < 4; j++)
            #pragma unroll
            for (int q = 0; q < 4; q++) acc[i][j][q] = 0.0f;

    const int ag   = lane >> 3;
    const int arow = (ag & 1) * 8 + (lane & 7);
    const int acu  = ag >> 1;
    const int lb   = lane & 15;
    const int bg   = lb >> 3;
    const int brow = lb & 7;

    load_stage(sb + 0 * STAGE_B, row0, nrow0, 0,  tid);
    load_stage(sb + 1 * STAGE_B, row0, nrow0, 32, tid);

    int stage = 0;
    for (int c = 0; c < 32; c++) {
        if (c + 1 < 32) {
            asm volatile("cp.async.wait_group 1;" ::: "memory");
        } else {
            asm volatile("cp.async.wait_group 0;" ::: "memory");
        }
        __syncthreads();
        if (c + 2 < 32) {
            int ns = stage + 2; if (ns >= 3) ns -= 3;
            load_stage(sb + ns * STAGE_B, row0, nrow0, (c + 2) * 32, tid);
        }

        const uint32_t st = sb + stage * STAGE_B;
        const uint32_t aA = st + 0 * TILE_B;
        const uint32_t aB = st + 1 * TILE_B;

        #pragma unroll
        for (int ks = 0; ks < 2; ks++) {
            uint32_t ah[2][4], bw[4][2];
            #pragma unroll
            for (int i = 0; i < 2; i++) {
                const uint32_t off = (uint32_t)((wm * 32 + i * 16 + arow) * ROW_B
                                                + (2 * ks + acu) * 16);
                ldm_x4(ah[i], aA + off);
            }
            #pragma unroll
            for (int j = 0; j < 4; j++) {
                const uint32_t off = (uint32_t)((wn * 32 + j * 8 + brow) * ROW_B
                                                + (2 * ks + bg) * 16);
                ldm_x2(bw[j], aB + off);
            }
            #pragma unroll
            for (int i = 0; i < 2; i++)
                #pragma unroll
                for (int j = 0; j < 4; j++)
                    mma_fp16(acc[i][j], ah[i], bw[j]);
        }
        if (++stage >= 3) stage = 0;
    }

    // Epilogue: bias + split to bf16 hi/lo
    const float* bias = (which == 0) ? bq : (which == 1) ? bk : bv;
    __nv_bfloat16* Outh = (which == 0) ? g_Qh : (which == 1) ? g_Kh : g_Vh;
    __nv_bfloat16* Outl = (which == 0) ? g_Ql : (which == 1) ? g_Kl : g_Vl;
    const int r0 = lane >> 2;
    const int c0 = (lane & 3) * 2;
    #pragma unroll
    for (int i = 0; i < 2; i++) {
        const int m0 = row0 + wm * 32 + i * 16 + r0;
        #pragma unroll
        for (int j = 0; j < 4; j++) {
            const int col = cm0 + wn * 32 + j * 8 + c0;
            const float b0 = bias[col], b1 = bias[col + 1];
            const float v0 = acc[i][j][0] + b0, v1 = acc[i][j][1] + b1;
            const float v2 = acc[i][j][2] + b0, v3 = acc[i][j][3] + b1;
            *reinterpret_cast<uint32_t*>(Outh + (size_t)m0 * HID + col) = pack_bf16(v0, v1);
            *reinterpret_cast<uint32_t*>(Outl + (size_t)m0 * HID + col) =
                pack_bf16(v0 - bf16_round(v0), v1 - bf16_round(v1));
            *reinterpret_cast<uint32_t*>(Outh + (size_t)(m0 + 8) * HID + col) = pack_bf16(v2, v3);
            *reinterpret_cast<uint32_t*>(Outl + (size_t)(m0 + 8) * HID + col) =
                pack_bf16(v2 - bf16_round(v2), v3 - bf16_round(v3));
        }
    }
}

// ---------------------------------------------------------------------------
// Kernel 2: tensor-core block-local attention, bf16x3 split QK^T and PV,
// online softmax over 4 chunks of 64 keys. One CTA per (b, g, n), 8 warps,
// warp w owns query rows [w*32, w*32+32).  (unchanged from R8/R10/R11)
// ---------------------------------------------------------------------------
#define QSTR 144                          // smem row stride bytes (128 data + 16 pad)
#define SOFF_QH 0
#define SOFF_QL (256 * QSTR)              // 36864
#define SOFF_KH (2 * 256 * QSTR)          // 73728
#define SOFF_KL (SOFF_KH + 64 * QSTR)
#define SOFF_VH (SOFF_KL + 64 * QSTR)
#define SOFF_VL (SOFF_VH + 64 * QSTR)
#define ATTN_SMEM (SOFF_VL + 64 * QSTR)   // 110592

__global__ __launch_bounds__(256) void attn_mma(
    const int* __restrict__ perm, float* __restrict__ out)
{
    extern __shared__ __align__(128) char smem[];
    const uint32_t sb = smem_u32(smem);
    const int n = blockIdx.x, g = blockIdx.y, b = blockIdx.z;
    const int tid = threadIdx.x, wid = tid >> 5, lane = tid & 31;

    const int p  = perm[g * NH + n];
    const int gs = p >> 4;
    const int ns = p & 15;

    // load Q hi/lo into smem (256 rows x 8 x 16B units each)
    const size_t qbase = ((size_t)(b * SEQ + g * BLK)) * HID + n * HD;
    for (int i = tid; i < 2048; i += 256) {
        const int r = i >> 3, u = i & 7;
        *reinterpret_cast<uint4*>(smem + SOFF_QH + r * QSTR + u * 16) =
            *reinterpret_cast<const uint4*>(g_Qh + qbase + (size_t)r * HID + u * 8);
        *reinterpret_cast<uint4*>(smem + SOFF_QL + r * QSTR + u * 16) =
            *reinterpret_cast<const uint4*>(g_Ql + qbase + (size_t)r * HID + u * 8);
    }

    float m[2][2], l[2][2], oacc[2][8][4];
    #pragma unroll
    for (int mt = 0; mt < 2; mt++)
        #pragma unroll
        for (int h = 0; h < 2; h++) { m[mt][h] = -1e30f; l[mt][h] = 0.0f; }
    #pragma unroll
    for (int mt = 0; mt < 2; mt++)
        #pragma unroll
        for (int nt = 0; nt < 8; nt++)
            #pragma unroll
            for (int q = 0; q < 4; q++) oacc[mt][nt][q] = 0.0f;

    const int ag   = lane >> 3;
    const int arow = (ag & 1) * 8 + (lane & 7);
    const int acu  = ag >> 1;
    const int lb   = lane & 15;
    const int bg   = lb >> 3;
    const int brow = lb & 7;

    const size_t kvbase = ((size_t)(b * SEQ + gs * BLK)) * HID + ns * HD;

    for (int c = 0; c < 4; c++) {
        __syncthreads();   // Q visible (c=0); prior chunk compute done (c>0)
        for (int i = tid; i < 512; i += 256) {
            const int r = i >> 3, u = i & 7;
            const size_t go = kvbase + (size_t)(c * 64 + r) * HID + u * 8;
            *reinterpret_cast<uint4*>(smem + SOFF_KH + r * QSTR + u * 16) =
                *reinterpret_cast<const uint4*>(g_Kh + go);
            *reinterpret_cast<uint4*>(smem + SOFF_KL + r * QSTR + u * 16) =
                *reinterpret_cast<const uint4*>(g_Kl + go);
            *reinterpret_cast<uint4*>(smem + SOFF_VH + r * QSTR + u * 16) =
                *reinterpret_cast<const uint4*>(g_Vh + go);
            *reinterpret_cast<uint4*>(smem + SOFF_VL + r * QSTR + u * 16) =
                *reinterpret_cast<const uint4*>(g_Vl + go);
        }
        __syncthreads();

        // ---- S = Q K^T (bf16x3) ----
        float sacc[2][8][4];
        #pragma unroll
        for (int mt = 0; mt < 2; mt++)
            #pragma unroll
            for (int nt = 0; nt < 8; nt++)
                #pragma unroll
                for (int q = 0; q < 4; q++) sacc[mt][nt][q] = 0.0f;

        #pragma unroll
        for (int ks = 0; ks < 4; ks++) {
            uint32_t aqh[2][4], aql[2][4];
            #pragma unroll
            for (int mt = 0; mt < 2; mt++) {
                const uint32_t ao = sb + SOFF_QH
                    + (uint32_t)((wid * 32 + mt * 16 + arow) * QSTR + ks * 32 + acu * 16);
                ldm_x4(aqh[mt], ao);
                ldm_x4(aql[mt], ao + (SOFF_QL - SOFF_QH));
            }
            #pragma unroll
            for (int nt = 0; nt < 8; nt++) {
                uint32_t bkh[2], bkl[2];
                const uint32_t bo = sb + SOFF_KH
                    + (uint32_t)((nt * 8 + brow) * QSTR + ks * 32 + bg * 16);
                ldm_x2(bkh, bo);
                ldm_x2(bkl, bo + (SOFF_KL - SOFF_KH));
                #pragma unroll
                for (int mt = 0; mt < 2; mt++) {
                    mma_bf16(sacc[mt][nt], aqh[mt], bkh);
                    mma_bf16(sacc[mt][nt], aqh[mt], bkl);
                    mma_bf16(sacc[mt][nt], aql[mt], bkh);
                }
            }
        }

        // ---- online softmax ----
        #pragma unroll
        for (int mt = 0; mt < 2; mt++) {
            #pragma unroll
            for (int h = 0; h < 2; h++) {
                float rmax = -1e30f;
                #pragma unroll
                for (int nt = 0; nt < 8; nt++) {
                    sacc[mt][nt][2*h]   *= 0.125f;
                    sacc[mt][nt][2*h+1] *= 0.125f;
                    rmax = fmaxf(rmax, fmaxf(sacc[mt][nt][2*h], sacc[mt][nt][2*h+1]));
                }
                rmax = fmaxf(rmax, __shfl_xor_sync(0xffffffff, rmax, 1));
                rmax = fmaxf(rmax, __shfl_xor_sync(0xffffffff, rmax, 2));
                const float mn   = fmaxf(m[mt][h], rmax);
                const float corr = __expf(m[mt][h] - mn);
                m[mt][h] = mn;
                float rsum = 0.0f;
                #pragma unroll
                for (int nt = 0; nt < 8; nt++) {
                    const float e0 = __expf(sacc[mt][nt][2*h]   - mn);
                    const float e1 = __expf(sacc[mt][nt][2*h+1] - mn);
                    sacc[mt][nt][2*h] = e0; sacc[mt][nt][2*h+1] = e1;
                    rsum += e0 + e1;
                    oacc[mt][nt][2*h]   *= corr;
                    oacc[mt][nt][2*h+1] *= corr;
                }
                rsum += __shfl_xor_sync(0xffffffff, rsum, 1);
                rsum += __shfl_xor_sync(0xffffffff, rsum, 2);
                l[mt][h] = l[mt][h] * corr + rsum;
            }
        }

        // ---- O += P V (bf16x3; P frags from C-register layout) ----
        #pragma unroll
        for (int ks = 0; ks < 4; ks++) {
            uint32_t aph[2][4], apl[2][4];
            #pragma unroll
            for (int mt = 0; mt < 2; mt++) {
                #pragma unroll
                for (int half = 0; half < 2; half++) {   // n-tiles 2ks, 2ks+1
                    const float* s4 = sacc[mt][2 * ks + half];
                    aph[mt][2*half]     = pack_bf16(s4[0], s4[1]);
                    aph[mt][2*half + 1] = pack_bf16(s4[2], s4[3]);
                    apl[mt][2*half]     = pack_bf16(s4[0] - bf16_round(s4[0]),
                                                    s4[1] - bf16_round(s4[1]));
                    apl[mt][2*half + 1] = pack_bf16(s4[2] - bf16_round(s4[2]),
                                                    s4[3] - bf16_round(s4[3]));
                }
            }
            #pragma unroll
            for (int nd = 0; nd < 8; nd++) {
                uint32_t bvh[2], bvl[2];
                const uint32_t vo = sb + SOFF_VH
                    + (uint32_t)((ks * 16 + lb) * QSTR + nd * 16);
                ldm_x2_t(bvh, vo);
                ldm_x2_t(bvl, vo + (SOFF_VL - SOFF_VH));
                #pragma unroll
                for (int mt = 0; mt < 2; mt++) {
                    mma_bf16(oacc[mt][nd], aph[mt], bvh);
                    mma_bf16(oacc[mt][nd], aph[mt], bvl);
                    mma_bf16(oacc[mt][nd], apl[mt], bvh);
                }
            }
        }
    }

    // ---- write O / l ----
    const int lr = lane >> 2;
    const int lc = (lane & 3) * 2;
    #pragma unroll
    for (int mt = 0; mt < 2; mt++) {
        #pragma unroll
        for (int h = 0; h < 2; h++) {
            const float inv = 1.0f / l[mt][h];
            const int row = g * BLK + wid * 32 + mt * 16 + lr + 8 * h;
            float* op = out + (((size_t)(b * SEQ + row)) * NH + n) * HD;
            #pragma unroll
            for (int nd = 0; nd < 8; nd++) {
                float2 v = make_float2(oacc[mt][nd][2*h] * inv, oacc[mt][nd][2*h+1] * inv);
                *reinterpret_cast<float2*>(op + nd * 8 + lc) = v;
            }
        }
    }
}

// ---------------------------------------------------------------------------
extern "C" void kernel_launch(void* const* d_in, const int* in_sizes, int n_in,
                              void* d_out, int out_size)
{
    const float* x    = (const float*)d_in[0];
    const int*   perm = (const int*)  d_in[2];
    const float* qw   = (const float*)d_in[3];
    const float* qb   = (const float*)d_in[4];
    const float* kw   = (const float*)d_in[5];
    const float* kb   = (const float*)d_in[6];
    const float* vw   = (const float*)d_in[7];
    const float* vb   = (const float*)d_in[8];
    float* out = (float*)d_out;

    split_A_kernel<<<MROWS * HID / 4 / 256, 256>>>(x);
    split_W_kernel<<<dim3(32, 32, 3), dim3(32, 8)>>>(qw, kw, vw);

    (void)cudaFuncSetAttribute(gemm_mma, cudaFuncAttributeMaxDynamicSharedMemorySize, GEMM_SMEM);
    gemm_mma<<<dim3(24, 64), 512, GEMM_SMEM>>>(qb, kb, vb);

    (void)cudaFuncSetAttribute(attn_mma, cudaFuncAttributeMaxDynamicSharedMemorySize, ATTN_SMEM);
    attn_mma<<<dim3(NH, NB, B_SZ), 256, ATTN_SMEM>>>(perm, out);
}

// round 15
// speedup vs baseline: 4.4974x; 1.1643x over previous
#include <cuda_runtime.h>
#include <cuda_bf16.h>
#include <cuda_fp16.h>
#include <cstdint>

// ---------------------------------------------------------------------------
// SelfAttention: QKV projection (mma.sync single-fp16 GEMM, K-chunk 64) +
// tensor-core block-local attention (16 q-rows/warp, 2 CTAs/SM).
// ---------------------------------------------------------------------------

#define B_SZ     2
#define SEQ      4096
#define HID      1024
#define NH       16
#define HD       64
#define NB       16
#define BLK      256
#define MROWS    (B_SZ * SEQ)          // 8192

// fp16 GEMM inputs: A single fp16, W single fp16 (transposed)
__device__ __half g_Ah[MROWS * HID];
__device__ __half g_Wt[3 * HID * HID];           // transposed: [n][k]

// bf16 hi/lo projected Q/K/V (GEMM outputs; attention inputs)
__device__ __nv_bfloat16 g_Qh[MROWS * HID];
__device__ __nv_bfloat16 g_Ql[MROWS * HID];
__device__ __nv_bfloat16 g_Kh[MROWS * HID];
__device__ __nv_bfloat16 g_Kl[MROWS * HID];
__device__ __nv_bfloat16 g_Vh[MROWS * HID];
__device__ __nv_bfloat16 g_Vl[MROWS * HID];

// ---------------------------------------------------------------------------
// PTX helpers (non-'a' features only: cp.async, ldmatrix, mma.sync)
// ---------------------------------------------------------------------------
__device__ __forceinline__ uint32_t smem_u32(const void* p) {
    uint32_t a;
    asm("{ .reg .u64 t; cvta.to.shared.u64 t, %1; cvt.u32.u64 %0, t; }"
        : "=r"(a) : "l"(p));
    return a;
}

__device__ __forceinline__ void cp16(uint32_t dst, const void* src) {
    asm volatile("cp.async.cg.shared.global [%0], [%1], 16;" :: "r"(dst), "l"(src));
}
#define CP_COMMIT() asm volatile("cp.async.commit_group;" ::: "memory")

__device__ __forceinline__ void ldm_x4(uint32_t* r, uint32_t addr) {
    asm volatile("ldmatrix.sync.aligned.m8n8.x4.shared.b16 {%0,%1,%2,%3}, [%4];"
                 : "=r"(r[0]), "=r"(r[1]), "=r"(r[2]), "=r"(r[3]) : "r"(addr));
}
__device__ __forceinline__ void ldm_x2(uint32_t* r, uint32_t addr) {
    asm volatile("ldmatrix.sync.aligned.m8n8.x2.shared.b16 {%0,%1}, [%2];"
                 : "=r"(r[0]), "=r"(r[1]) : "r"(addr));
}
__device__ __forceinline__ void ldm_x2_t(uint32_t* r, uint32_t addr) {
    asm volatile("ldmatrix.sync.aligned.m8n8.x2.trans.shared.b16 {%0,%1}, [%2];"
                 : "=r"(r[0]), "=r"(r[1]) : "r"(addr));
}
__device__ __forceinline__ void mma_bf16(float* c, const uint32_t* a, const uint32_t* b) {
    asm volatile(
        "mma.sync.aligned.m16n8k16.row.col.f32.bf16.bf16.f32 "
        "{%0,%1,%2,%3}, {%4,%5,%6,%7}, {%8,%9}, {%0,%1,%2,%3};"
        : "+f"(c[0]), "+f"(c[1]), "+f"(c[2]), "+f"(c[3])
        : "r"(a[0]), "r"(a[1]), "r"(a[2]), "r"(a[3]), "r"(b[0]), "r"(b[1]));
}
__device__ __forceinline__ void mma_fp16(float* c, const uint32_t* a, const uint32_t* b) {
    asm volatile(
        "mma.sync.aligned.m16n8k16.row.col.f32.f16.f16.f32 "
        "{%0,%1,%2,%3}, {%4,%5,%6,%7}, {%8,%9}, {%0,%1,%2,%3};"
        : "+f"(c[0]), "+f"(c[1]), "+f"(c[2]), "+f"(c[3])
        : "r"(a[0]), "r"(a[1]), "r"(a[2]), "r"(a[3]), "r"(b[0]), "r"(b[1]));
}

// pack two floats -> bf16x2 (lo in low half)
__device__ __forceinline__ uint32_t pack_bf16(float lo, float hi) {
    uint32_t r;
    asm("cvt.rn.bf16x2.f32 %0, %1, %2;" : "=r"(r) : "f"(hi), "f"(lo));
    return r;
}
__device__ __forceinline__ float bf16_round(float x) {
    return __bfloat162float(__float2bfloat16(x));
}

// ---------------------------------------------------------------------------
// Pre-pass 1: convert A to fp16
// ---------------------------------------------------------------------------
__global__ __launch_bounds__(256) void split_A_kernel(const float* __restrict__ x) {
    const int i = blockIdx.x * 256 + threadIdx.x;     // one float4 per thread
    float4 v = reinterpret_cast<const float4*>(x)[i];
    __half2* ph = reinterpret_cast<__half2*>(g_Ah) + 2 * i;
    __half2 t0, t1;
    t0.x = __float2half(v.x); t0.y = __float2half(v.y);
    t1.x = __float2half(v.z); t1.y = __float2half(v.w);
    ph[0] = t0;
    ph[1] = t1;
}

// ---------------------------------------------------------------------------
// Pre-pass 2: transpose weights to fp16.  wt[n][k] = fp16(w[k][n]).
// grid (32, 32, 3), block (32, 8)
// ---------------------------------------------------------------------------
__global__ __launch_bounds__(256) void split_W_kernel(
    const float* __restrict__ qw, const float* __restrict__ kw, const float* __restrict__ vw) {
    __shared__ float tile[32][33];
    const int mat = blockIdx.z;
    const float* src = (mat == 0) ? qw : (mat == 1) ? kw : vw;
    const int n0 = blockIdx.x * 32;
    const int k0 = blockIdx.y * 32;
    const int tx = threadIdx.x, ty = threadIdx.y;

    #pragma unroll
    for (int j = 0; j < 32; j += 8)
        tile[ty + j][tx] = src[(size_t)(k0 + ty + j) * HID + n0 + tx];
    __syncthreads();

    __half* dh = g_Wt + (size_t)mat * HID * HID;
    #pragma unroll
    for (int j = 0; j < 32; j += 8)
        dh[(size_t)(n0 + ty + j) * HID + k0 + tx] = __float2half(tile[tx][ty + j]);
}

// ---------------------------------------------------------------------------
// Main GEMM: C[8192, 3*1024] = A * Wt^T + bias, single fp16 via mma.sync.
// 512 threads (16 warps), CTA tile 128x128, warp tile 32x32 (4m x 4n grid),
// K chunk 64, 3-stage cp.async pipeline, one __syncthreads per chunk.
// Row stride 144B (36 banks) -> ldmatrix conflict-free.
// ---------------------------------------------------------------------------
#define GROW     144
#define GTILE    (128 * GROW)             // 18432
#define GSTAGE   (2 * GTILE)              // 36864
#define GEMM_SMEM (3 * GSTAGE)            // 110592

__device__ __forceinline__ void load_stage(
    uint32_t sstage, int row0, int nrow0, int kt, int tid) {
    const __half* srcs[2] = {
        g_Ah + (size_t)row0  * HID,
        g_Wt + (size_t)nrow0 * HID };
    #pragma unroll
    for (int rep = 0; rep < 2; rep++) {
        const int idx = tid + rep * 512;  // 0..1023: 128 rows x 8 units
        const int r = idx >> 3;
        const int u = idx & 7;
        #pragma unroll
        for (int t = 0; t < 2; t++) {
            cp16(sstage + t * GTILE + r * GROW + u * 16,
                 srcs[t] + (size_t)r * HID + kt + u * 8);
        }
    }
    CP_COMMIT();
}

__global__ __launch_bounds__(512) void gemm_mma(
    const float* __restrict__ bq, const float* __restrict__ bk, const float* __restrict__ bv) {
    extern __shared__ __align__(128) char smem[];
    const uint32_t sb = smem_u32(smem);
    const int tid  = threadIdx.x;
    const int wid  = tid >> 5;           // 0..15
    const int lane = tid & 31;
    const int wm   = wid & 3;            // m quarter: rows wm*32
    const int wn   = wid >> 2;           // n quarter: cols wn*32

    const int t     = blockIdx.x;        // 0..23
    const int row0  = blockIdx.y * 128;
    const int which = t >> 3;
    const int nrow0 = t * 128;
    const int cm0   = (t & 7) * 128;

    float acc[2][4][4];
    #pragma unroll
    for (int i = 0; i < 2; i++)
        #pragma unroll
        for (int j = 0; j < 4; j++)
            #pragma unroll
            for (int q = 0; q < 4; q++) acc[i][j][q] = 0.0f;

    const int ag   = lane >> 3;
    const int arow = (ag & 1) * 8 + (lane & 7);
    const int acu  = ag >> 1;
    const int lb   = lane & 15;
    const int bg   = lb >> 3;
    const int brow = lb & 7;

    load_stage(sb + 0 * GSTAGE, row0, nrow0, 0,  tid);
    load_stage(sb + 1 * GSTAGE, row0, nrow0, 64, tid);

    int stage = 0;
    for (int c = 0; c < 16; c++) {
        if (c + 1 < 16) {
            asm volatile("cp.async.wait_group 1;" ::: "memory");
        } else {
            asm volatile("cp.async.wait_group 0;" ::: "memory");
        }
        __syncthreads();
        if (c + 2 < 16) {
            int ns = stage + 2; if (ns >= 3) ns -= 3;
            load_stage(sb + ns * GSTAGE, row0, nrow0, (c + 2) * 64, tid);
        }

        const uint32_t st = sb + stage * GSTAGE;
        const uint32_t aA = st + 0 * GTILE;
        const uint32_t aB = st + 1 * GTILE;

        #pragma unroll
        for (int ks = 0; ks < 4; ks++) {
            uint32_t ah[2][4], bw[4][2];
            #pragma unroll
            for (int i = 0; i < 2; i++) {
                const uint32_t off = (uint32_t)((wm * 32 + i * 16 + arow) * GROW
                                                + (2 * ks + acu) * 16);
                ldm_x4(ah[i], aA + off);
            }
            #pragma unroll
            for (int j = 0; j < 4; j++) {
                const uint32_t off = (uint32_t)((wn * 32 + j * 8 + brow) * GROW
                                                + (2 * ks + bg) * 16);
                ldm_x2(bw[j], aB + off);
            }
            #pragma unroll
            for (int i = 0; i < 2; i++)
                #pragma unroll
                for (int j = 0; j < 4; j++)
                    mma_fp16(acc[i][j], ah[i], bw[j]);
        }
        if (++stage >= 3) stage = 0;
    }

    // Epilogue: bias + split to bf16 hi/lo
    const float* bias = (which == 0) ? bq : (which == 1) ? bk : bv;
    __nv_bfloat16* Outh = (which == 0) ? g_Qh : (which == 1) ? g_Kh : g_Vh;
    __nv_bfloat16* Outl = (which == 0) ? g_Ql : (which == 1) ? g_Kl : g_Vl;
    const int r0 = lane >> 2;
    const int c0 = (lane & 3) * 2;
    #pragma unroll
    for (int i = 0; i < 2; i++) {
        const int m0 = row0 + wm * 32 + i * 16 + r0;
        #pragma unroll
        for (int j = 0; j < 4; j++) {
            const int col = cm0 + wn * 32 + j * 8 + c0;
            const float b0 = bias[col], b1 = bias[col + 1];
            const float v0 = acc[i][j][0] + b0, v1 = acc[i][j][1] + b1;
            const float v2 = acc[i][j][2] + b0, v3 = acc[i][j][3] + b1;
            *reinterpret_cast<uint32_t*>(Outh + (size_t)m0 * HID + col) = pack_bf16(v0, v1);
            *reinterpret_cast<uint32_t*>(Outl + (size_t)m0 * HID + col) =
                pack_bf16(v0 - bf16_round(v0), v1 - bf16_round(v1));
            *reinterpret_cast<uint32_t*>(Outh + (size_t)(m0 + 8) * HID + col) = pack_bf16(v2, v3);
            *reinterpret_cast<uint32_t*>(Outl + (size_t)(m0 + 8) * HID + col) =
                pack_bf16(v2 - bf16_round(v2), v3 - bf16_round(v3));
        }
    }
}

// ---------------------------------------------------------------------------
// Kernel 2: tensor-core block-local attention, bf16x3 split QK^T and PV.
// Re-tiled for occupancy: one CTA per (b, g-half, n) covering 128 q-rows,
// 8 warps x 16 q-rows, grid (16, 32, 2), 2 CTAs/SM target.
// ---------------------------------------------------------------------------
#define QSTR 144                          // smem row stride bytes (128 data + 16 pad)
#define SOFF_QH 0
#define SOFF_QL (128 * QSTR)              // 18432
#define SOFF_KH (2 * 128 * QSTR)          // 36864
#define SOFF_KL (SOFF_KH + 64 * QSTR)
#define SOFF_VH (SOFF_KL + 64 * QSTR)
#define SOFF_VL (SOFF_VH + 64 * QSTR)
#define ATTN_SMEM (SOFF_VL + 64 * QSTR)   // 73728

__global__ __launch_bounds__(256, 2) void attn_mma(
    const int* __restrict__ perm, float* __restrict__ out)
{
    extern __shared__ __align__(128) char smem[];
    const uint32_t sb = smem_u32(smem);
    const int n = blockIdx.x;
    const int g = blockIdx.y >> 1;
    const int qh = blockIdx.y & 1;        // which 128-row half of the q block
    const int b = blockIdx.z;
    const int tid = threadIdx.x, wid = tid >> 5, lane = tid & 31;

    const int p  = perm[g * NH + n];
    const int gs = p >> 4;
    const int ns = p & 15;

    // load Q hi/lo into smem (128 rows x 8 x 16B units each)
    const size_t qbase = ((size_t)(b * SEQ + g * BLK + qh * 128)) * HID + n * HD;
    for (int i = tid; i < 1024; i += 256) {
        const int r = i >> 3, u = i & 7;
        *reinterpret_cast<uint4*>(smem + SOFF_QH + r * QSTR + u * 16) =
            *reinterpret_cast<const uint4*>(g_Qh + qbase + (size_t)r * HID + u * 8);
        *reinterpret_cast<uint4*>(smem + SOFF_QL + r * QSTR + u * 16) =
            *reinterpret_cast<const uint4*>(g_Ql + qbase + (size_t)r * HID + u * 8);
    }

    float m[2], l[2], oacc[8][4];
    #pragma unroll
    for (int h = 0; h < 2; h++) { m[h] = -1e30f; l[h] = 0.0f; }
    #pragma unroll
    for (int nt = 0; nt < 8; nt++)
        #pragma unroll
        for (int q = 0; q < 4; q++) oacc[nt][q] = 0.0f;

    const int ag   = lane >> 3;
    const int arow = (ag & 1) * 8 + (lane & 7);
    const int acu  = ag >> 1;
    const int lb   = lane & 15;
    const int bg   = lb >> 3;
    const int brow = lb & 7;

    const size_t kvbase = ((size_t)(b * SEQ + gs * BLK)) * HID + ns * HD;

    for (int c = 0; c < 4; c++) {
        __syncthreads();   // Q visible (c=0); prior chunk compute done (c>0)
        for (int i = tid; i < 512; i += 256) {
            const int r = i >> 3, u = i & 7;
            const size_t go = kvbase + (size_t)(c * 64 + r) * HID + u * 8;
            *reinterpret_cast<uint4*>(smem + SOFF_KH + r * QSTR + u * 16) =
                *reinterpret_cast<const uint4*>(g_Kh + go);
            *reinterpret_cast<uint4*>(smem + SOFF_KL + r * QSTR + u * 16) =
                *reinterpret_cast<const uint4*>(g_Kl + go);
            *reinterpret_cast<uint4*>(smem + SOFF_VH + r * QSTR + u * 16) =
                *reinterpret_cast<const uint4*>(g_Vh + go);
            *reinterpret_cast<uint4*>(smem + SOFF_VL + r * QSTR + u * 16) =
                *reinterpret_cast<const uint4*>(g_Vl + go);
        }
        __syncthreads();

        // ---- S = Q K^T (bf16x3) ----
        float sacc[8][4];
        #pragma unroll
        for (int nt = 0; nt < 8; nt++)
            #pragma unroll
            for (int q = 0; q < 4; q++) sacc[nt][q] = 0.0f;

        #pragma unroll
        for (int ks = 0; ks < 4; ks++) {
            uint32_t aqh[4], aql[4];
            const uint32_t ao = sb + SOFF_QH
                + (uint32_t)((wid * 16 + arow) * QSTR + ks * 32 + acu * 16);
            ldm_x4(aqh, ao);
            ldm_x4(aql, ao + (SOFF_QL - SOFF_QH));
            #pragma unroll
            for (int nt = 0; nt < 8; nt++) {
                uint32_t bkh[2], bkl[2];
                const uint32_t bo = sb + SOFF_KH
                    + (uint32_t)((nt * 8 + brow) * QSTR + ks * 32 + bg * 16);
                ldm_x2(bkh, bo);
                ldm_x2(bkl, bo + (SOFF_KL - SOFF_KH));
                mma_bf16(sacc[nt], aqh, bkh);
                mma_bf16(sacc[nt], aqh, bkl);
                mma_bf16(sacc[nt], aql, bkh);
            }
        }

        // ---- online softmax ----
        #pragma unroll
        for (int h = 0; h < 2; h++) {
            float rmax = -1e30f;
            #pragma unroll
            for (int nt = 0; nt < 8; nt++) {
                sacc[nt][2*h]   *= 0.125f;
                sacc[nt][2*h+1] *= 0.125f;
                rmax = fmaxf(rmax, fmaxf(sacc[nt][2*h], sacc[nt][2*h+1]));
            }
            rmax = fmaxf(rmax, __shfl_xor_sync(0xffffffff, rmax, 1));
            rmax = fmaxf(rmax, __shfl_xor_sync(0xffffffff, rmax, 2));
            const float mn   = fmaxf(m[h], rmax);
            const float corr = __expf(m[h] - mn);
            m[h] = mn;
            float rsum = 0.0f;
            #pragma unroll
            for (int nt = 0; nt < 8; nt++) {
                const float e0 = __expf(sacc[nt][2*h]   - mn);
                const float e1 = __expf(sacc[nt][2*h+1] - mn);
                sacc[nt][2*h] = e0; sacc[nt][2*h+1] = e1;
                rsum += e0 + e1;
                oacc[nt][2*h]   *= corr;
                oacc[nt][2*h+1] *= corr;
            }
            rsum += __shfl_xor_sync(0xffffffff, rsum, 1);
            rsum += __shfl_xor_sync(0xffffffff, rsum, 2);
            l[h] = l[h] * corr + rsum;
        }

        // ---- O += P V (bf16x3; P frags from C-register layout) ----
        #pragma unroll
        for (int ks = 0; ks < 4; ks++) {
            uint32_t aph[4], apl[4];
            #pragma unroll
            for (int half = 0; half < 2; half++) {   // n-tiles 2ks, 2ks+1
                const float* s4 = sacc[2 * ks + half];
                aph[2*half]     = pack_bf16(s4[0], s4[1]);
                aph[2*half + 1] = pack_bf16(s4[2], s4[3]);
                apl[2*half]     = pack_bf16(s4[0] - bf16_round(s4[0]),
                                            s4[1] - bf16_round(s4[1]));
                apl[2*half + 1] = pack_bf16(s4[2] - bf16_round(s4[2]),
                                            s4[3] - bf16_round(s4[3]));
            }
            #pragma unroll
            for (int nd = 0; nd < 8; nd++) {
                uint32_t bvh[2], bvl[2];
                const uint32_t vo = sb + SOFF_VH
                    + (uint32_t)((ks * 16 + lb) * QSTR + nd * 16);
                ldm_x2_t(bvh, vo);
                ldm_x2_t(bvl, vo + (SOFF_VL - SOFF_VH));
                mma_bf16(oacc[nd], aph, bvh);
                mma_bf16(oacc[nd], aph, bvl);
                mma_bf16(oacc[nd], apl, bvh);
            }
        }
    }

    // ---- write O / l ----
    const int lr = lane >> 2;
    const int lc = (lane & 3) * 2;
    #pragma unroll
    for (int h = 0; h < 2; h++) {
        const float inv = 1.0f / l[h];
        const int row = g * BLK + qh * 128 + wid * 16 + lr + 8 * h;
        float* op = out + (((size_t)(b * SEQ + row)) * NH + n) * HD;
        #pragma unroll
        for (int nd = 0; nd < 8; nd++) {
            float2 v = make_float2(oacc[nd][2*h] * inv, oacc[nd][2*h+1] * inv);
            *reinterpret_cast<float2*>(op + nd * 8 + lc) = v;
        }
    }
}

// ---------------------------------------------------------------------------
extern "C" void kernel_launch(void* const* d_in, const int* in_sizes, int n_in,
                              void* d_out, int out_size)
{
    const float* x    = (const float*)d_in[0];
    const int*   perm = (const int*)  d_in[2];
    const float* qw   = (const float*)d_in[3];
    const float* qb   = (const float*)d_in[4];
    const float* kw   = (const float*)d_in[5];
    const float* kb   = (const float*)d_in[6];
    const float* vw   = (const float*)d_in[7];
    const float* vb   = (const float*)d_in[8];
    float* out = (float*)d_out;

    split_A_kernel<<<MROWS * HID / 4 / 256, 256>>>(x);
    split_W_kernel<<<dim3(32, 32, 3), dim3(32, 8)>>>(qw, kw, vw);

    (void)cudaFuncSetAttribute(gemm_mma, cudaFuncAttributeMaxDynamicSharedMemorySize, GEMM_SMEM);
    gemm_mma<<<dim3(24, 64), 512, GEMM_SMEM>>>(qb, kb, vb);

    (void)cudaFuncSetAttribute(attn_mma, cudaFuncAttributeMaxDynamicSharedMemorySize, ATTN_SMEM);
    attn_mma<<<dim3(NH, NB * 2, B_SZ), 256, ATTN_SMEM>>>(perm, out);
}